// round 11
// baseline (speedup 1.0000x reference)
#include <cuda_runtime.h>
#include <cuda_fp16.h>

#define NHH 8
#define KD 32
#define HD 32
#define OC 1280     // NH*(4*KD+HD)
#define DIN 256
#define NPIX 4096   // 64*64
#define BB 2
#define OPH 160     // channels per head
#define SCALE 0.17677669529663687f

typedef unsigned long long u64;
typedef unsigned int u32;

__device__ float g_p[BB * OC * NPIX];        // projection output [b][o][pix]
__device__ float g_R[BB * NHH * 64 * NPIX];  // row-attn weights R[bH][i][pix]
__device__ float g_C[BB * NHH * 64 * NPIX];  // col-attn weights C[bH][j][pix]

// ---- packed f32x2 helpers ----
__device__ __forceinline__ u64 ffma2(u64 a, u64 b, u64 c) {
    u64 d;
    asm("fma.rn.f32x2 %0, %1, %2, %3;" : "=l"(d) : "l"(a), "l"(b), "l"(c));
    return d;
}
__device__ __forceinline__ u64 fdup(float v) {
    u64 d;
    asm("mov.b64 %0, {%1, %1};" : "=l"(d) : "f"(v));
    return d;
}
__device__ __forceinline__ float lo32(u64 v) { return __uint_as_float((unsigned)v); }
__device__ __forceinline__ float hi32(u64 v) { return __uint_as_float((unsigned)(v >> 32)); }

__device__ __forceinline__ u32 smem_u32(const void* p) {
    u32 a;
    asm("{ .reg .u64 t; cvta.to.shared.u64 t, %1; cvt.u32.u64 %0, t; }" : "=r"(a) : "l"(p));
    return a;
}
__device__ __forceinline__ u32 h2u(__half2 h) { return *(u32*)&h; }

// ---------------- Kernel 1: projection GEMM  p[b,o,pix] = sum_c w[o,c] x[b,c,pix]
__global__ __launch_bounds__(256) void k_proj(const float* __restrict__ x,
                                              const float* __restrict__ w) {
    __shared__ float As[16][64];  // [k][m]
    __shared__ float Bs[16][64];  // [k][n]
    const int b  = blockIdx.z;
    const int m0 = blockIdx.y * 64;
    const int n0 = blockIdx.x * 64;
    const float* xb = x + (size_t)b * DIN * NPIX;
    const int t  = threadIdx.x;
    const int tm = t >> 4, tn = t & 15;
    const int lm = t >> 2, lk4 = (t & 3) * 4;
    const int lk = t >> 4, ln4 = (t & 15) * 4;
    u64 acc[4][2] = {};
    for (int k0 = 0; k0 < DIN; k0 += 16) {
        float4 a4 = *(const float4*)&w[(m0 + lm) * DIN + k0 + lk4];
        As[lk4 + 0][lm] = a4.x; As[lk4 + 1][lm] = a4.y;
        As[lk4 + 2][lm] = a4.z; As[lk4 + 3][lm] = a4.w;
        *(float4*)&Bs[lk][ln4] = *(const float4*)&xb[(k0 + lk) * NPIX + n0 + ln4];
        __syncthreads();
#pragma unroll
        for (int kk = 0; kk < 16; kk++) {
            float4 av = *(const float4*)&As[kk][tm * 4];
            ulonglong2 bv = *(const ulonglong2*)&Bs[kk][tn * 4];
            u64 a2[4] = {fdup(av.x), fdup(av.y), fdup(av.z), fdup(av.w)};
#pragma unroll
            for (int ii = 0; ii < 4; ii++) {
                acc[ii][0] = ffma2(a2[ii], bv.x, acc[ii][0]);
                acc[ii][1] = ffma2(a2[ii], bv.y, acc[ii][1]);
            }
        }
        __syncthreads();
    }
    float* pp = g_p + (size_t)b * OC * NPIX;
#pragma unroll
    for (int ii = 0; ii < 4; ii++) {
        float4 o = {lo32(acc[ii][0]), hi32(acc[ii][0]),
                    lo32(acc[ii][1]), hi32(acc[ii][1])};
        *(float4*)&pp[(m0 + tm * 4 + ii) * NPIX + n0 + tn * 4] = o;
    }
}

// ---------------- Kernel 2: row attention.  Block per (b,H,w).
__global__ __launch_bounds__(256) void k_rowattn() {
    __shared__ float sq[32][64];
    __shared__ float sk[32][64];
    __shared__ float A[64][65];
    const int w = blockIdx.x, H = blockIdx.y, b = blockIdx.z;
    const int t = threadIdx.x;
    const float* pq = g_p + ((size_t)(b * OC) + H * OPH) * NPIX;
    const float* pk = pq + (size_t)KD * NPIX;
    for (int idx = t; idx < 32 * 64; idx += 256) {
        int d = idx >> 6, i = idx & 63;
        sq[d][i] = pq[(size_t)d * NPIX + i * 64 + w];
        sk[d][i] = pk[(size_t)d * NPIX + i * 64 + w];
    }
    __syncthreads();
    {
        const int ti = (t >> 4) * 4, tj = (t & 15) * 4;
        float acc[4][4] = {};
#pragma unroll 8
        for (int d = 0; d < 32; d++) {
            float4 av = *(const float4*)&sq[d][ti];
            float4 bv = *(const float4*)&sk[d][tj];
            float a[4] = {av.x, av.y, av.z, av.w};
            float bb2[4] = {bv.x, bv.y, bv.z, bv.w};
#pragma unroll
            for (int ii = 0; ii < 4; ii++)
#pragma unroll
                for (int jj = 0; jj < 4; jj++)
                    acc[ii][jj] = fmaf(a[ii], bb2[jj], acc[ii][jj]);
        }
#pragma unroll
        for (int ii = 0; ii < 4; ii++)
#pragma unroll
            for (int jj = 0; jj < 4; jj++)
                A[ti + ii][tj + jj] = acc[ii][jj] * SCALE;
    }
    __syncthreads();
    const int wid = t >> 5, lane = t & 31;
    float* Rb = g_R + (size_t)(b * NHH + H) * 64 * NPIX;
#pragma unroll
    for (int jj = 0; jj < 8; jj++) {
        int j = wid * 8 + jj;
        float v0 = A[lane][j], v1 = A[lane + 32][j];
        float m = fmaxf(v0, v1);
#pragma unroll
        for (int s = 16; s; s >>= 1) m = fmaxf(m, __shfl_xor_sync(0xffffffffu, m, s));
        float e0 = __expf(v0 - m), e1 = __expf(v1 - m);
        float sm = e0 + e1;
#pragma unroll
        for (int s = 16; s; s >>= 1) sm += __shfl_xor_sync(0xffffffffu, sm, s);
        float inv = 1.0f / sm;
        Rb[(size_t)lane * NPIX + j * 64 + w] = e0 * inv;
        Rb[(size_t)(lane + 32) * NPIX + j * 64 + w] = e1 * inv;
    }
}

// ---------------- Kernel 3: column attention.  Block per (b,H,h).
__global__ __launch_bounds__(256) void k_colattn() {
    __shared__ float sq[32][64];
    __shared__ float sk[32][64];
    __shared__ float A[64][65];
    const int h = blockIdx.x, H = blockIdx.y, b = blockIdx.z;
    const int t = threadIdx.x;
    const float* pq = g_p + ((size_t)(b * OC) + H * OPH + 2 * KD) * NPIX + h * 64;
    const float* pk = g_p + ((size_t)(b * OC) + H * OPH + 3 * KD) * NPIX + h * 64;
#pragma unroll
    for (int u = 0; u < 2; u++) {
        int e = t + u * 256;
        int d = e >> 4, c4 = (e & 15) * 4;
        *(float4*)&sq[d][c4] = *(const float4*)&pq[(size_t)d * NPIX + c4];
        *(float4*)&sk[d][c4] = *(const float4*)&pk[(size_t)d * NPIX + c4];
    }
    __syncthreads();
    {
        const int ti = (t >> 4) * 4, tj = (t & 15) * 4;
        float acc[4][4] = {};
#pragma unroll 8
        for (int d = 0; d < 32; d++) {
            float4 av = *(const float4*)&sq[d][ti];
            float4 bv = *(const float4*)&sk[d][tj];
            float a[4] = {av.x, av.y, av.z, av.w};
            float bb2[4] = {bv.x, bv.y, bv.z, bv.w};
#pragma unroll
            for (int ii = 0; ii < 4; ii++)
#pragma unroll
                for (int jj = 0; jj < 4; jj++)
                    acc[ii][jj] = fmaf(a[ii], bb2[jj], acc[ii][jj]);
        }
#pragma unroll
        for (int ii = 0; ii < 4; ii++)
#pragma unroll
            for (int jj = 0; jj < 4; jj++)
                A[ti + ii][tj + jj] = acc[ii][jj] * SCALE;
    }
    __syncthreads();
    const int wid = t >> 5, lane = t & 31;
#pragma unroll
    for (int jj = 0; jj < 8; jj++) {
        int j = wid * 8 + jj;
        float v0 = A[lane][j], v1 = A[lane + 32][j];
        float m = fmaxf(v0, v1);
#pragma unroll
        for (int s = 16; s; s >>= 1) m = fmaxf(m, __shfl_xor_sync(0xffffffffu, m, s));
        float e0 = __expf(v0 - m), e1 = __expf(v1 - m);
        float sm = e0 + e1;
#pragma unroll
        for (int s = 16; s; s >>= 1) sm += __shfl_xor_sync(0xffffffffu, sm, s);
        float inv = 1.0f / sm;
        A[lane][j] = e0 * inv;
        A[lane + 32][j] = e1 * inv;
    }
    __syncthreads();
    float* Cb = g_C + (size_t)(b * NHH + H) * 64 * NPIX + h * 64;
    for (int idx = t; idx < 64 * 64; idx += 256) {
        int jj = idx >> 6, ww = idx & 63;
        Cb[(size_t)jj * NPIX + ww] = A[jj][ww];
    }
}

// ---------------- Kernel 4 (mma.sync fp16): D[p,d] = sum_k G[p,k] V[d,k]; out = D + V
// C-frags hoisted into registers (invariant over slabs), R resident fp16 in SMEM,
// V slab double-buffered (1 sync/slab).
// SMEM: Cs [128][72] h (18432) | Vs0 (4608) | Vs1 (4608) | Rsh [64][128] h (16384)
#define SM_CS 0
#define SM_VS0 18432
#define SM_VS1 23040
#define SM_RS 27648
#define SM_FINAL 44032

__global__ __launch_bounds__(256) void k_final(float* __restrict__ out) {
    extern __shared__ char smc[];
    __half* Cs  = (__half*)(smc + SM_CS);
    __half* Rsh = (__half*)(smc + SM_RS);
    float* Ds   = (float*)(smc + SM_CS);   // overlay after mainloop

    const int t = threadIdx.x, warp = t >> 5, lane = t & 31;
    const int p0 = blockIdx.x * 128;
    const int H = blockIdx.y, b = blockIdx.z;
    const int bH = b * NHH + H;
    const float* Rg = g_R + (size_t)bH * 64 * NPIX + p0;
    const float* Cg = g_C + (size_t)bH * 64 * NPIX + p0;
    const float* Vg = g_p + ((size_t)(b * OC) + H * OPH + 4 * KD) * NPIX;

    // Cs[p][j] = half(C[j][p])  — coalesced along p
#pragma unroll
    for (int u = 0; u < 16; u++) {
        int e = t + u * 256;
        int j2 = e >> 7, p = e & 127;
        __half2 hv = __floats2half2_rn(Cg[(size_t)(2 * j2) * NPIX + p],
                                       Cg[(size_t)(2 * j2 + 1) * NPIX + p]);
        *(__half2*)&Cs[p * 72 + j2 * 2] = hv;
    }
    // Rsh[i][p] = half(R[i][p])
#pragma unroll
    for (int u = 0; u < 8; u++) {
        int e = t + u * 256;
        int i = e >> 5, p4 = (e & 31) * 4;
        float4 r4 = *(const float4*)&Rg[(size_t)i * NPIX + p4];
        __half2 a = __floats2half2_rn(r4.x, r4.y);
        __half2 bh = __floats2half2_rn(r4.z, r4.w);
        uint2 pk = {h2u(a), h2u(bh)};
        *(uint2*)&Rsh[i * 128 + p4] = pk;
    }

    const int prow = lane >> 2, qpair = lane & 3;
    const int pl = warp * 16 + prow;
    const int bl = lane & 15;
    const int brow = bl & 7, bk8 = (bl >> 3) * 8;
    const int vd = t >> 3, vj = (t & 7) * 8;

    // Build V slab 0
    {
        float4 v0 = *(const float4*)&Vg[(size_t)vd * NPIX + vj];
        float4 v1 = *(const float4*)&Vg[(size_t)vd * NPIX + vj + 4];
        uint4 o;
        __half2* oh = (__half2*)&o;
        oh[0] = __floats2half2_rn(v0.x, v0.y);
        oh[1] = __floats2half2_rn(v0.z, v0.w);
        oh[2] = __floats2half2_rn(v1.x, v1.y);
        oh[3] = __floats2half2_rn(v1.z, v1.w);
        *(uint4*)((smc + SM_VS0) + (vd * 72 + vj) * 2) = o;
    }
    __syncthreads();

    // Hoist C-fragments into registers (invariant across slabs)
    u32 cf[4][4];
#pragma unroll
    for (int ks = 0; ks < 4; ks++) {
        int j0 = ks * 16 + qpair * 2;
        cf[ks][0] = h2u(*(__half2*)&Cs[pl * 72 + j0]);
        cf[ks][1] = h2u(*(__half2*)&Cs[(pl + 8) * 72 + j0]);
        cf[ks][2] = h2u(*(__half2*)&Cs[pl * 72 + j0 + 8]);
        cf[ks][3] = h2u(*(__half2*)&Cs[(pl + 8) * 72 + j0 + 8]);
    }

    float acc[4][4] = {};

    for (int s = 0; s < 64; s++) {
        char* Vcur = smc + ((s & 1) ? SM_VS1 : SM_VS0);
        // prefetch/build next slab into the other buffer (no sync needed before:
        // buffer s+1 was last read at slab s-1, separated by the sync below)
        if (s < 63) {
            char* Vnxt = smc + ((s & 1) ? SM_VS0 : SM_VS1);
            float4 v0 = *(const float4*)&Vg[(size_t)vd * NPIX + (s + 1) * 64 + vj];
            float4 v1 = *(const float4*)&Vg[(size_t)vd * NPIX + (s + 1) * 64 + vj + 4];
            uint4 o;
            __half2* oh = (__half2*)&o;
            oh[0] = __floats2half2_rn(v0.x, v0.y);
            oh[1] = __floats2half2_rn(v0.z, v0.w);
            oh[2] = __floats2half2_rn(v1.x, v1.y);
            oh[3] = __floats2half2_rn(v1.z, v1.w);
            *(uint4*)(Vnxt + (vd * 72 + vj) * 2) = o;
        }
        __half2 rlo = __half2half2(Rsh[s * 128 + pl]);
        __half2 rhi = __half2half2(Rsh[s * 128 + pl + 8]);
#pragma unroll
        for (int ks = 0; ks < 4; ks++) {
            u32 a0 = h2u(__hmul2(rlo, *(__half2*)&cf[ks][0]));
            u32 a1 = h2u(__hmul2(rhi, *(__half2*)&cf[ks][1]));
            u32 a2 = h2u(__hmul2(rlo, *(__half2*)&cf[ks][2]));
            u32 a3 = h2u(__hmul2(rhi, *(__half2*)&cf[ks][3]));
#pragma unroll
            for (int nt = 0; nt < 4; nt++) {
                u32 baddr = smem_u32(Vcur + ((nt * 8 + brow) * 72 + ks * 16 + bk8) * 2);
                u32 b0, b1;
                asm volatile("ldmatrix.sync.aligned.m8n8.x2.shared.b16 {%0,%1}, [%2];"
                             : "=r"(b0), "=r"(b1) : "r"(baddr));
                asm volatile(
                    "mma.sync.aligned.m16n8k16.row.col.f32.f16.f16.f32 "
                    "{%0,%1,%2,%3}, {%4,%5,%6,%7}, {%8,%9}, {%0,%1,%2,%3};"
                    : "+f"(acc[nt][0]), "+f"(acc[nt][1]),
                      "+f"(acc[nt][2]), "+f"(acc[nt][3])
                    : "r"(a0), "r"(a1), "r"(a2), "r"(a3), "r"(b0), "r"(b1));
            }
        }
        __syncthreads();
    }

    // epilogue: transpose through SMEM (Ds overlays Cs), add residual, store
#pragma unroll
    for (int nt = 0; nt < 4; nt++) {
        int d = nt * 8 + qpair * 2;
        Ds[d * 132 + pl]           = acc[nt][0];
        Ds[(d + 1) * 132 + pl]     = acc[nt][1];
        Ds[d * 132 + pl + 8]       = acc[nt][2];
        Ds[(d + 1) * 132 + pl + 8] = acc[nt][3];
    }
    __syncthreads();
#pragma unroll
    for (int u = 0; u < 4; u++) {
        int e = t + u * 256;
        int d = e >> 5, p4 = (e & 31) * 4;
        float4 r = *(const float4*)&Vg[(size_t)d * NPIX + p0 + p4];
        float4 v = *(const float4*)&Ds[d * 132 + p4];
        float4 o = {v.x + r.x, v.y + r.y, v.z + r.z, v.w + r.w};
        *(float4*)&out[((size_t)(b * 256) + H * 32 + d) * NPIX + p0 + p4] = o;
    }
}

extern "C" void kernel_launch(void* const* d_in, const int* in_sizes, int n_in,
                              void* d_out, int out_size) {
    const float* x = (const float*)d_in[0];
    const float* w = (const float*)d_in[1];
    if (n_in >= 2 && in_sizes[0] == OC * DIN) {
        const float* tmp = x; x = w; w = tmp;
    }
    float* out = (float*)d_out;

    k_proj<<<dim3(64, 20, BB), 256>>>(x, w);
    k_rowattn<<<dim3(64, NHH, BB), 256>>>();
    k_colattn<<<dim3(64, NHH, BB), 256>>>();
    k_final<<<dim3(32, NHH, BB), 256, SM_FINAL>>>(out);
}

// round 12
// speedup vs baseline: 1.1280x; 1.1280x over previous
#include <cuda_runtime.h>
#include <cuda_fp16.h>

#define NHH 8
#define KD 32
#define HD 32
#define OC 1280     // NH*(4*KD+HD)
#define DIN 256
#define NPIX 4096   // 64*64
#define BB 2
#define OPH 160     // channels per head
#define SCALE 0.17677669529663687f

typedef unsigned long long u64;
typedef unsigned int u32;

__device__ float g_p[BB * OC * NPIX];           // projection output [b][o][pix]
__device__ __half g_Rh[BB * NHH * 64 * NPIX];   // row-attn weights fp16 [bH][i][pix]
__device__ __half g_ChT[BB * NHH * NPIX * 64];  // col-attn weights fp16, p-major [bH][pix][j]
__device__ __half g_vh[BB * NHH * 32 * NPIX];   // V fp16 [bH][d][pix]

// ---- packed f32x2 helpers ----
__device__ __forceinline__ u64 ffma2(u64 a, u64 b, u64 c) {
    u64 d;
    asm("fma.rn.f32x2 %0, %1, %2, %3;" : "=l"(d) : "l"(a), "l"(b), "l"(c));
    return d;
}
__device__ __forceinline__ u64 fdup(float v) {
    u64 d;
    asm("mov.b64 %0, {%1, %1};" : "=l"(d) : "f"(v));
    return d;
}
__device__ __forceinline__ float lo32(u64 v) { return __uint_as_float((unsigned)v); }
__device__ __forceinline__ float hi32(u64 v) { return __uint_as_float((unsigned)(v >> 32)); }

__device__ __forceinline__ u32 smem_u32(const void* p) {
    u32 a;
    asm("{ .reg .u64 t; cvta.to.shared.u64 t, %1; cvt.u32.u64 %0, t; }" : "=r"(a) : "l"(p));
    return a;
}
__device__ __forceinline__ u32 h2u(__half2 h) { return *(u32*)&h; }

// ---------------- Kernel 1: projection GEMM  p[b,o,pix] = sum_c w[o,c] x[b,c,pix]
__global__ __launch_bounds__(256) void k_proj(const float* __restrict__ x,
                                              const float* __restrict__ w) {
    __shared__ float As[16][64];  // [k][m]
    __shared__ float Bs[16][64];  // [k][n]
    const int b  = blockIdx.z;
    const int m0 = blockIdx.y * 64;
    const int n0 = blockIdx.x * 64;
    const float* xb = x + (size_t)b * DIN * NPIX;
    const int t  = threadIdx.x;
    const int tm = t >> 4, tn = t & 15;
    const int lm = t >> 2, lk4 = (t & 3) * 4;
    const int lk = t >> 4, ln4 = (t & 15) * 4;
    u64 acc[4][2] = {};
    for (int k0 = 0; k0 < DIN; k0 += 16) {
        float4 a4 = *(const float4*)&w[(m0 + lm) * DIN + k0 + lk4];
        As[lk4 + 0][lm] = a4.x; As[lk4 + 1][lm] = a4.y;
        As[lk4 + 2][lm] = a4.z; As[lk4 + 3][lm] = a4.w;
        *(float4*)&Bs[lk][ln4] = *(const float4*)&xb[(k0 + lk) * NPIX + n0 + ln4];
        __syncthreads();
#pragma unroll
        for (int kk = 0; kk < 16; kk++) {
            float4 av = *(const float4*)&As[kk][tm * 4];
            ulonglong2 bv = *(const ulonglong2*)&Bs[kk][tn * 4];
            u64 a2[4] = {fdup(av.x), fdup(av.y), fdup(av.z), fdup(av.w)};
#pragma unroll
            for (int ii = 0; ii < 4; ii++) {
                acc[ii][0] = ffma2(a2[ii], bv.x, acc[ii][0]);
                acc[ii][1] = ffma2(a2[ii], bv.y, acc[ii][1]);
            }
        }
        __syncthreads();
    }
    float* pp = g_p + (size_t)b * OC * NPIX;
#pragma unroll
    for (int ii = 0; ii < 4; ii++) {
        float4 o = {lo32(acc[ii][0]), hi32(acc[ii][0]),
                    lo32(acc[ii][1]), hi32(acc[ii][1])};
        *(float4*)&pp[(m0 + tm * 4 + ii) * NPIX + n0 + tn * 4] = o;
    }
}

// ---------------- Prep: V slice of g_p -> fp16 g_vh [bH][d][pix]
__global__ __launch_bounds__(256) void k_prep_v() {
    int gid = blockIdx.x * 256 + threadIdx.x;   // each handles 8 halves
    int bH = gid >> 14;                          // 32*4096/8 = 16384 per bH
    int rem = gid & 16383;
    int d = rem >> 9;                            // 512 groups of 8 per d
    int p8 = (rem & 511) * 8;
    int b = bH >> 3, H = bH & 7;
    const float* src = g_p + ((size_t)(b * OC) + H * OPH + 4 * KD + d) * NPIX + p8;
    float4 v0 = *(const float4*)src;
    float4 v1 = *(const float4*)(src + 4);
    uint4 o;
    __half2* oh = (__half2*)&o;
    oh[0] = __floats2half2_rn(v0.x, v0.y);
    oh[1] = __floats2half2_rn(v0.z, v0.w);
    oh[2] = __floats2half2_rn(v1.x, v1.y);
    oh[3] = __floats2half2_rn(v1.z, v1.w);
    *(uint4*)&g_vh[((size_t)bH * 32 + d) * NPIX + p8] = o;
}

// ---------------- Kernel 2: row attention.  Block per (b,H,w).  Writes fp16 R.
__global__ __launch_bounds__(256) void k_rowattn() {
    __shared__ float sq[32][64];
    __shared__ float sk[32][64];
    __shared__ float A[64][65];
    const int w = blockIdx.x, H = blockIdx.y, b = blockIdx.z;
    const int t = threadIdx.x;
    const float* pq = g_p + ((size_t)(b * OC) + H * OPH) * NPIX;
    const float* pk = pq + (size_t)KD * NPIX;
    for (int idx = t; idx < 32 * 64; idx += 256) {
        int d = idx >> 6, i = idx & 63;
        sq[d][i] = pq[(size_t)d * NPIX + i * 64 + w];
        sk[d][i] = pk[(size_t)d * NPIX + i * 64 + w];
    }
    __syncthreads();
    {
        const int ti = (t >> 4) * 4, tj = (t & 15) * 4;
        float acc[4][4] = {};
#pragma unroll 8
        for (int d = 0; d < 32; d++) {
            float4 av = *(const float4*)&sq[d][ti];
            float4 bv = *(const float4*)&sk[d][tj];
            float a[4] = {av.x, av.y, av.z, av.w};
            float bb2[4] = {bv.x, bv.y, bv.z, bv.w};
#pragma unroll
            for (int ii = 0; ii < 4; ii++)
#pragma unroll
                for (int jj = 0; jj < 4; jj++)
                    acc[ii][jj] = fmaf(a[ii], bb2[jj], acc[ii][jj]);
        }
#pragma unroll
        for (int ii = 0; ii < 4; ii++)
#pragma unroll
            for (int jj = 0; jj < 4; jj++)
                A[ti + ii][tj + jj] = acc[ii][jj] * SCALE;
    }
    __syncthreads();
    const int wid = t >> 5, lane = t & 31;
    __half* Rb = g_Rh + (size_t)(b * NHH + H) * 64 * NPIX;
#pragma unroll
    for (int jj = 0; jj < 8; jj++) {
        int j = wid * 8 + jj;
        float v0 = A[lane][j], v1 = A[lane + 32][j];
        float m = fmaxf(v0, v1);
#pragma unroll
        for (int s = 16; s; s >>= 1) m = fmaxf(m, __shfl_xor_sync(0xffffffffu, m, s));
        float e0 = __expf(v0 - m), e1 = __expf(v1 - m);
        float sm = e0 + e1;
#pragma unroll
        for (int s = 16; s; s >>= 1) sm += __shfl_xor_sync(0xffffffffu, sm, s);
        float inv = 1.0f / sm;
        Rb[(size_t)lane * NPIX + j * 64 + w] = __float2half_rn(e0 * inv);
        Rb[(size_t)(lane + 32) * NPIX + j * 64 + w] = __float2half_rn(e1 * inv);
    }
}

// ---------------- Kernel 3: column attention.  Block per (b,H,h).  Writes fp16 C^T (p-major).
__global__ __launch_bounds__(256) void k_colattn() {
    __shared__ float sq[32][64];
    __shared__ float sk[32][64];
    __shared__ float A[64][65];
    const int h = blockIdx.x, H = blockIdx.y, b = blockIdx.z;
    const int t = threadIdx.x;
    const float* pq = g_p + ((size_t)(b * OC) + H * OPH + 2 * KD) * NPIX + h * 64;
    const float* pk = g_p + ((size_t)(b * OC) + H * OPH + 3 * KD) * NPIX + h * 64;
#pragma unroll
    for (int u = 0; u < 2; u++) {
        int e = t + u * 256;
        int d = e >> 4, c4 = (e & 15) * 4;
        *(float4*)&sq[d][c4] = *(const float4*)&pq[(size_t)d * NPIX + c4];
        *(float4*)&sk[d][c4] = *(const float4*)&pk[(size_t)d * NPIX + c4];
    }
    __syncthreads();
    {
        const int ti = (t >> 4) * 4, tj = (t & 15) * 4;
        float acc[4][4] = {};
#pragma unroll 8
        for (int d = 0; d < 32; d++) {
            float4 av = *(const float4*)&sq[d][ti];
            float4 bv = *(const float4*)&sk[d][tj];
            float a[4] = {av.x, av.y, av.z, av.w};
            float bb2[4] = {bv.x, bv.y, bv.z, bv.w};
#pragma unroll
            for (int ii = 0; ii < 4; ii++)
#pragma unroll
                for (int jj = 0; jj < 4; jj++)
                    acc[ii][jj] = fmaf(a[ii], bb2[jj], acc[ii][jj]);
        }
#pragma unroll
        for (int ii = 0; ii < 4; ii++)
#pragma unroll
            for (int jj = 0; jj < 4; jj++)
                A[ti + ii][tj + jj] = acc[ii][jj] * SCALE;
    }
    __syncthreads();
    const int wid = t >> 5, lane = t & 31;
#pragma unroll
    for (int jj = 0; jj < 8; jj++) {
        int j = wid * 8 + jj;
        float v0 = A[lane][j], v1 = A[lane + 32][j];
        float m = fmaxf(v0, v1);
#pragma unroll
        for (int s = 16; s; s >>= 1) m = fmaxf(m, __shfl_xor_sync(0xffffffffu, m, s));
        float e0 = __expf(v0 - m), e1 = __expf(v1 - m);
        float sm = e0 + e1;
#pragma unroll
        for (int s = 16; s; s >>= 1) sm += __shfl_xor_sync(0xffffffffu, sm, s);
        float inv = 1.0f / sm;
        A[lane][j] = e0 * inv;
        A[lane + 32][j] = e1 * inv;
    }
    __syncthreads();
    // write transposed p-major fp16: g_ChT[bH][h*64+ww][jj]
    {
        const int bH = b * NHH + H;
        const int ww = t >> 2, jj0 = (t & 3) * 16;
        __half* Cp = g_ChT + ((size_t)bH * NPIX + h * 64 + ww) * 64 + jj0;
        uint4 o[2];
        __half2* oh = (__half2*)o;
#pragma unroll
        for (int q = 0; q < 8; q++)
            oh[q] = __floats2half2_rn(A[jj0 + 2 * q][ww], A[jj0 + 2 * q + 1][ww]);
        *(uint4*)Cp = o[0];
        *(uint4*)(Cp + 8) = o[1];
    }
}

// ---------------- Kernel 4 (mma.sync fp16 + cp.async pipeline)
// D[p,d] = sum_k G[p,k] V[d,k]; out = D + V.  Per CTA: (b,H), 128-p tile.
// V slabs streamed global->SMEM via 4-stage cp.async ring (prefetch distance 3).
// C-fragments: 16 registers loaded once from g_ChT. R: 2 LDG.16/slab (L1 broadcast).
// SMEM: 4 stages x 32 rows x 144B = 18432 B; epilogue Ds (32x132 f32) overlays.
#define VROWB 144
#define STAGE_BYTES 4608

__global__ __launch_bounds__(256) void k_final(float* __restrict__ out) {
    __shared__ char smc[4 * STAGE_BYTES];
    float* Ds = (float*)smc;   // overlay after mainloop

    const int t = threadIdx.x, warp = t >> 5, lane = t & 31;
    const int p0 = blockIdx.x * 128;
    const int H = blockIdx.y, b = blockIdx.z;
    const int bH = b * NHH + H;
    const __half* Rh = g_Rh + (size_t)bH * 64 * NPIX + p0;
    const __half* Ct = g_ChT + ((size_t)bH * NPIX + p0) * 64;
    const __half* Vh = g_vh + (size_t)bH * 32 * NPIX;
    const float* Vg = g_p + ((size_t)(b * OC) + H * OPH + 4 * KD) * NPIX;

    const int prow = lane >> 2, qpair = lane & 3;
    const int pl = warp * 16 + prow;
    const int bl = lane & 15;
    const int brow = bl & 7, bk8 = (bl >> 3) * 8;
    const int vd = t >> 3, vc = (t & 7) * 8;   // cp.async: row d, col offset (halves)

    // C-fragments: invariant across all 64 slabs — load once from global
    u32 cf[4][4];
#pragma unroll
    for (int ks = 0; ks < 4; ks++) {
        int j0 = ks * 16 + qpair * 2;
        cf[ks][0] = *(const u32*)&Ct[(size_t)pl * 64 + j0];
        cf[ks][1] = *(const u32*)&Ct[(size_t)(pl + 8) * 64 + j0];
        cf[ks][2] = *(const u32*)&Ct[(size_t)pl * 64 + j0 + 8];
        cf[ks][3] = *(const u32*)&Ct[(size_t)(pl + 8) * 64 + j0 + 8];
    }

#define ISSUE_SLAB(s) do { \
    u32 dst = smem_u32(smc + ((s) & 3) * STAGE_BYTES + vd * VROWB + vc * 2); \
    const __half* src = Vh + (size_t)vd * NPIX + (s) * 64 + vc; \
    asm volatile("cp.async.cg.shared.global [%0], [%1], 16;" :: "r"(dst), "l"(src)); \
} while (0)
#define COMMIT() asm volatile("cp.async.commit_group;")

    ISSUE_SLAB(0); COMMIT();
    ISSUE_SLAB(1); COMMIT();
    ISSUE_SLAB(2); COMMIT();

    float acc[4][4] = {};

    for (int s = 0; s < 64; s++) {
        asm volatile("cp.async.wait_group 2;");
        __syncthreads();
        char* Vcur = smc + (s & 3) * STAGE_BYTES;
        __half2 rlo = __half2half2(Rh[(size_t)s * NPIX + pl]);
        __half2 rhi = __half2half2(Rh[(size_t)s * NPIX + pl + 8]);
#pragma unroll
        for (int ks = 0; ks < 4; ks++) {
            u32 a0 = h2u(__hmul2(rlo, *(__half2*)&cf[ks][0]));
            u32 a1 = h2u(__hmul2(rhi, *(__half2*)&cf[ks][1]));
            u32 a2 = h2u(__hmul2(rlo, *(__half2*)&cf[ks][2]));
            u32 a3 = h2u(__hmul2(rhi, *(__half2*)&cf[ks][3]));
#pragma unroll
            for (int nt = 0; nt < 4; nt++) {
                u32 baddr = smem_u32(Vcur + (nt * 8 + brow) * VROWB + (ks * 16 + bk8) * 2);
                u32 b0, b1;
                asm volatile("ldmatrix.sync.aligned.m8n8.x2.shared.b16 {%0,%1}, [%2];"
                             : "=r"(b0), "=r"(b1) : "r"(baddr));
                asm volatile(
                    "mma.sync.aligned.m16n8k16.row.col.f32.f16.f16.f32 "
                    "{%0,%1,%2,%3}, {%4,%5,%6,%7}, {%8,%9}, {%0,%1,%2,%3};"
                    : "+f"(acc[nt][0]), "+f"(acc[nt][1]),
                      "+f"(acc[nt][2]), "+f"(acc[nt][3])
                    : "r"(a0), "r"(a1), "r"(a2), "r"(a3), "r"(b0), "r"(b1));
            }
        }
        // prefetch slab s+3 into the stage last read at slab s-1
        if (s + 3 < 64) ISSUE_SLAB(s + 3);
        COMMIT();
    }
    asm volatile("cp.async.wait_group 0;");
    __syncthreads();

    // epilogue: transpose through SMEM (Ds overlays V stages), add residual, store
#pragma unroll
    for (int nt = 0; nt < 4; nt++) {
        int d = nt * 8 + qpair * 2;
        Ds[d * 132 + pl]           = acc[nt][0];
        Ds[(d + 1) * 132 + pl]     = acc[nt][1];
        Ds[d * 132 + pl + 8]       = acc[nt][2];
        Ds[(d + 1) * 132 + pl + 8] = acc[nt][3];
    }
    __syncthreads();
#pragma unroll
    for (int u = 0; u < 4; u++) {
        int e = t + u * 256;
        int d = e >> 5, p4 = (e & 31) * 4;
        float4 r = *(const float4*)&Vg[(size_t)d * NPIX + p0 + p4];
        float4 v = *(const float4*)&Ds[d * 132 + p4];
        float4 o = {v.x + r.x, v.y + r.y, v.z + r.z, v.w + r.w};
        *(float4*)&out[((size_t)(b * 256) + H * 32 + d) * NPIX + p0 + p4] = o;
    }
}

extern "C" void kernel_launch(void* const* d_in, const int* in_sizes, int n_in,
                              void* d_out, int out_size) {
    const float* x = (const float*)d_in[0];
    const float* w = (const float*)d_in[1];
    if (n_in >= 2 && in_sizes[0] == OC * DIN) {
        const float* tmp = x; x = w; w = tmp;
    }
    float* out = (float*)d_out;

    k_proj<<<dim3(64, 20, BB), 256>>>(x, w);
    k_prep_v<<<1024, 256>>>();
    k_rowattn<<<dim3(64, NHH, BB), 256>>>();
    k_colattn<<<dim3(64, NHH, BB), 256>>>();
    k_final<<<dim3(32, NHH, BB), 256>>>(out);
}

// round 13
// speedup vs baseline: 1.4403x; 1.2768x over previous
#include <cuda_runtime.h>
#include <cuda_fp16.h>

#define NHH 8
#define KD 32
#define HD 32
#define OC 1280     // NH*(4*KD+HD)
#define DIN 256
#define NPIX 4096   // 64*64
#define BB 2
#define OPH 160     // channels per head
#define SCALE 0.17677669529663687f

typedef unsigned long long u64;
typedef unsigned int u32;

__device__ float g_p[BB * OC * NPIX];           // projection output [b][o][pix]
__device__ __half g_Rh[BB * NHH * 64 * NPIX];   // row-attn weights fp16 [bH][i][pix]
__device__ __half g_ChT[BB * NHH * NPIX * 64];  // col-attn weights fp16, p-major [bH][pix][j]
__device__ __half g_vh[BB * NHH * 32 * NPIX];   // V fp16 [bH][d][pix]
__device__ __half g_wh[OC * DIN];               // w hi fp16
__device__ __half g_wl[OC * DIN];               // w lo fp16 (residual)
__device__ __half g_xth[BB * NPIX * DIN];       // x^T hi fp16 [b][pix][c]
__device__ __half g_xtl[BB * NPIX * DIN];       // x^T lo fp16

__device__ __forceinline__ u32 smem_u32(const void* p) {
    u32 a;
    asm("{ .reg .u64 t; cvta.to.shared.u64 t, %1; cvt.u32.u64 %0, t; }" : "=r"(a) : "l"(p));
    return a;
}
__device__ __forceinline__ u32 h2u(__half2 h) { return *(u32*)&h; }

// ---------------- Prep A: w -> hi/lo fp16
__global__ __launch_bounds__(256) void k_prep_w(const float* __restrict__ w) {
    int gid = blockIdx.x * 256 + threadIdx.x;      // handles 2 elements
    if (gid * 2 >= OC * DIN) return;
    float2 v = *(const float2*)&w[gid * 2];
    __half h0 = __float2half_rn(v.x), h1 = __float2half_rn(v.y);
    __half l0 = __float2half_rn(v.x - __half2float(h0));
    __half l1 = __float2half_rn(v.y - __half2float(h1));
    ((__half2*)g_wh)[gid] = __halves2half2(h0, h1);
    ((__half2*)g_wl)[gid] = __halves2half2(l0, l1);
}

// ---------------- Prep B: x[c][pix] -> x^T[pix][c] hi/lo fp16 (32x32 smem transpose)
__global__ __launch_bounds__(256) void k_prep_xt(const float* __restrict__ x) {
    __shared__ float sx[32][33];
    const int b = blockIdx.z, c0 = blockIdx.y * 32, p0 = blockIdx.x * 32;
    const int t = threadIdx.x;
    const float* xb = x + (size_t)b * DIN * NPIX;
#pragma unroll
    for (int u = 0; u < 4; u++) {
        int ci = (t >> 5) + u * 8, pi = t & 31;
        sx[ci][pi] = xb[(size_t)(c0 + ci) * NPIX + p0 + pi];
    }
    __syncthreads();
#pragma unroll
    for (int u = 0; u < 4; u++) {
        int pi = (t >> 5) + u * 8, ci = t & 31;
        float v = sx[ci][pi];
        __half h = __float2half_rn(v);
        __half l = __float2half_rn(v - __half2float(h));
        size_t idx = ((size_t)b * NPIX + p0 + pi) * DIN + c0 + ci;
        g_xth[idx] = h;
        g_xtl[idx] = l;
    }
}

// ---------------- Kernel 1: projection via mma.sync fp16 3-way split (~fp32 accuracy)
// D[o][pix] = sum_k w[o][k] x[k][pix].  CTA: 128o x 64pix, 8 warps (4m x 2n).
// Epilogue also emits fp16 V channels (o%OPH >= 128) into g_vh.
__global__ __launch_bounds__(256) void k_projt() {
    __shared__ __half Ash[128 * 40], Asl[128 * 40];
    __shared__ __half Bsh[64 * 40], Bsl[64 * 40];
    const int b = blockIdx.z;
    const int m0 = blockIdx.y * 128;
    const int n0 = blockIdx.x * 64;
    const int t = threadIdx.x, warp = t >> 5, lane = t & 31;
    const int warp_m = warp >> 1, warp_n = warp & 1;
    const int obase = warp_m * 32, pbase = warp_n * 32;
    const int prow = lane >> 2, qp = lane & 3;
    const int arow = (lane & 7) + ((lane >> 3) & 1) * 8;   // A x4 row-within-16
    const int acol = ((lane >> 4) & 1) * 8;                // A x4 k-half
    const int bl = lane & 15;
    const int brow = bl & 7, bk8 = (bl >> 3) * 8;          // B x2
    const int lar = t >> 1, lac = (t & 1) * 16;            // A loader
    const int lbr = t >> 2, lbc = (t & 3) * 8;             // B loader

    float acc[2][4][4] = {};

    for (int kc = 0; kc < 8; kc++) {
        const int k0 = kc * 32;
        if (kc) __syncthreads();
        {
            size_t wa = (size_t)(m0 + lar) * DIN + k0 + lac;
            *(uint4*)&Ash[lar * 40 + lac]     = *(const uint4*)&g_wh[wa];
            *(uint4*)&Ash[lar * 40 + lac + 8] = *(const uint4*)&g_wh[wa + 8];
            *(uint4*)&Asl[lar * 40 + lac]     = *(const uint4*)&g_wl[wa];
            *(uint4*)&Asl[lar * 40 + lac + 8] = *(const uint4*)&g_wl[wa + 8];
            size_t xa = ((size_t)b * NPIX + n0 + lbr) * DIN + k0 + lbc;
            *(uint4*)&Bsh[lbr * 40 + lbc] = *(const uint4*)&g_xth[xa];
            *(uint4*)&Bsl[lbr * 40 + lbc] = *(const uint4*)&g_xtl[xa];
        }
        __syncthreads();
#pragma unroll
        for (int kh = 0; kh < 2; kh++) {
            const int kk = kh * 16;
            u32 aH[2][4], aL[2][4], bH[4][2], bL[4][2];
#pragma unroll
            for (int mt = 0; mt < 2; mt++) {
                u32 aaddr = smem_u32(&Ash[(obase + mt * 16 + arow) * 40 + kk + acol]);
                asm volatile("ldmatrix.sync.aligned.m8n8.x4.shared.b16 {%0,%1,%2,%3}, [%4];"
                             : "=r"(aH[mt][0]), "=r"(aH[mt][1]), "=r"(aH[mt][2]), "=r"(aH[mt][3])
                             : "r"(aaddr));
                u32 aaddr2 = smem_u32(&Asl[(obase + mt * 16 + arow) * 40 + kk + acol]);
                asm volatile("ldmatrix.sync.aligned.m8n8.x4.shared.b16 {%0,%1,%2,%3}, [%4];"
                             : "=r"(aL[mt][0]), "=r"(aL[mt][1]), "=r"(aL[mt][2]), "=r"(aL[mt][3])
                             : "r"(aaddr2));
            }
#pragma unroll
            for (int nt = 0; nt < 4; nt++) {
                u32 baddr = smem_u32(&Bsh[(pbase + nt * 8 + brow) * 40 + kk + bk8]);
                asm volatile("ldmatrix.sync.aligned.m8n8.x2.shared.b16 {%0,%1}, [%2];"
                             : "=r"(bH[nt][0]), "=r"(bH[nt][1]) : "r"(baddr));
                u32 baddr2 = smem_u32(&Bsl[(pbase + nt * 8 + brow) * 40 + kk + bk8]);
                asm volatile("ldmatrix.sync.aligned.m8n8.x2.shared.b16 {%0,%1}, [%2];"
                             : "=r"(bL[nt][0]), "=r"(bL[nt][1]) : "r"(baddr2));
            }
#pragma unroll
            for (int mt = 0; mt < 2; mt++)
#pragma unroll
                for (int nt = 0; nt < 4; nt++) {
#define MMA(AF, BF) \
    asm volatile("mma.sync.aligned.m16n8k16.row.col.f32.f16.f16.f32 " \
                 "{%0,%1,%2,%3}, {%4,%5,%6,%7}, {%8,%9}, {%0,%1,%2,%3};" \
                 : "+f"(acc[mt][nt][0]), "+f"(acc[mt][nt][1]), \
                   "+f"(acc[mt][nt][2]), "+f"(acc[mt][nt][3]) \
                 : "r"(AF[mt][0]), "r"(AF[mt][1]), "r"(AF[mt][2]), "r"(AF[mt][3]), \
                   "r"(BF[nt][0]), "r"(BF[nt][1]))
                    MMA(aH, bH);
                    MMA(aH, bL);
                    MMA(aL, bH);
#undef MMA
                }
        }
    }
    float* pp = g_p + (size_t)b * OC * NPIX;
#pragma unroll
    for (int mt = 0; mt < 2; mt++) {
        int o = m0 + obase + mt * 16 + prow;
#pragma unroll
        for (int nt = 0; nt < 4; nt++) {
            int pix = n0 + pbase + nt * 8 + qp * 2;
            *(float2*)&pp[(size_t)o * NPIX + pix] =
                make_float2(acc[mt][nt][0], acc[mt][nt][1]);
            *(float2*)&pp[(size_t)(o + 8) * NPIX + pix] =
                make_float2(acc[mt][nt][2], acc[mt][nt][3]);
        }
        // fused fp16 V emit (channels o%OPH in [128,160))
#pragma unroll
        for (int half_off = 0; half_off < 2; half_off++) {
            int oo = o + half_off * 8;
            int Hh = oo / OPH, c = oo % OPH;
            if (c >= 4 * KD) {
                int d = c - 4 * KD;
                __half* vdst = g_vh + ((size_t)(b * NHH + Hh) * 32 + d) * NPIX;
#pragma unroll
                for (int nt = 0; nt < 4; nt++) {
                    int pix = n0 + pbase + nt * 8 + qp * 2;
                    *(__half2*)&vdst[pix] =
                        __floats2half2_rn(acc[mt][nt][half_off * 2],
                                          acc[mt][nt][half_off * 2 + 1]);
                }
            }
        }
    }
}

// ---------------- Kernel 2: row attention.  Block per (b,H,w).  Writes fp16 R.
__global__ __launch_bounds__(256) void k_rowattn() {
    __shared__ float sq[32][64];
    __shared__ float sk[32][64];
    __shared__ float A[64][65];
    const int w = blockIdx.x, H = blockIdx.y, b = blockIdx.z;
    const int t = threadIdx.x;
    const float* pq = g_p + ((size_t)(b * OC) + H * OPH) * NPIX;
    const float* pk = pq + (size_t)KD * NPIX;
    for (int idx = t; idx < 32 * 64; idx += 256) {
        int d = idx >> 6, i = idx & 63;
        sq[d][i] = pq[(size_t)d * NPIX + i * 64 + w];
        sk[d][i] = pk[(size_t)d * NPIX + i * 64 + w];
    }
    __syncthreads();
    {
        const int ti = (t >> 4) * 4, tj = (t & 15) * 4;
        float acc[4][4] = {};
#pragma unroll 8
        for (int d = 0; d < 32; d++) {
            float4 av = *(const float4*)&sq[d][ti];
            float4 bv = *(const float4*)&sk[d][tj];
            float a[4] = {av.x, av.y, av.z, av.w};
            float bb2[4] = {bv.x, bv.y, bv.z, bv.w};
#pragma unroll
            for (int ii = 0; ii < 4; ii++)
#pragma unroll
                for (int jj = 0; jj < 4; jj++)
                    acc[ii][jj] = fmaf(a[ii], bb2[jj], acc[ii][jj]);
        }
#pragma unroll
        for (int ii = 0; ii < 4; ii++)
#pragma unroll
            for (int jj = 0; jj < 4; jj++)
                A[ti + ii][tj + jj] = acc[ii][jj] * SCALE;
    }
    __syncthreads();
    const int wid = t >> 5, lane = t & 31;
    __half* Rb = g_Rh + (size_t)(b * NHH + H) * 64 * NPIX;
#pragma unroll
    for (int jj = 0; jj < 8; jj++) {
        int j = wid * 8 + jj;
        float v0 = A[lane][j], v1 = A[lane + 32][j];
        float m = fmaxf(v0, v1);
#pragma unroll
        for (int s = 16; s; s >>= 1) m = fmaxf(m, __shfl_xor_sync(0xffffffffu, m, s));
        float e0 = __expf(v0 - m), e1 = __expf(v1 - m);
        float sm = e0 + e1;
#pragma unroll
        for (int s = 16; s; s >>= 1) sm += __shfl_xor_sync(0xffffffffu, sm, s);
        float inv = 1.0f / sm;
        Rb[(size_t)lane * NPIX + j * 64 + w] = __float2half_rn(e0 * inv);
        Rb[(size_t)(lane + 32) * NPIX + j * 64 + w] = __float2half_rn(e1 * inv);
    }
}

// ---------------- Kernel 3: column attention.  Block per (b,H,h).  Writes fp16 C^T (p-major).
__global__ __launch_bounds__(256) void k_colattn() {
    __shared__ float sq[32][64];
    __shared__ float sk[32][64];
    __shared__ float A[64][65];
    const int h = blockIdx.x, H = blockIdx.y, b = blockIdx.z;
    const int t = threadIdx.x;
    const float* pq = g_p + ((size_t)(b * OC) + H * OPH + 2 * KD) * NPIX + h * 64;
    const float* pk = g_p + ((size_t)(b * OC) + H * OPH + 3 * KD) * NPIX + h * 64;
#pragma unroll
    for (int u = 0; u < 2; u++) {
        int e = t + u * 256;
        int d = e >> 4, c4 = (e & 15) * 4;
        *(float4*)&sq[d][c4] = *(const float4*)&pq[(size_t)d * NPIX + c4];
        *(float4*)&sk[d][c4] = *(const float4*)&pk[(size_t)d * NPIX + c4];
    }
    __syncthreads();
    {
        const int ti = (t >> 4) * 4, tj = (t & 15) * 4;
        float acc[4][4] = {};
#pragma unroll 8
        for (int d = 0; d < 32; d++) {
            float4 av = *(const float4*)&sq[d][ti];
            float4 bv = *(const float4*)&sk[d][tj];
            float a[4] = {av.x, av.y, av.z, av.w};
            float bb2[4] = {bv.x, bv.y, bv.z, bv.w};
#pragma unroll
            for (int ii = 0; ii < 4; ii++)
#pragma unroll
                for (int jj = 0; jj < 4; jj++)
                    acc[ii][jj] = fmaf(a[ii], bb2[jj], acc[ii][jj]);
        }
#pragma unroll
        for (int ii = 0; ii < 4; ii++)
#pragma unroll
            for (int jj = 0; jj < 4; jj++)
                A[ti + ii][tj + jj] = acc[ii][jj] * SCALE;
    }
    __syncthreads();
    const int wid = t >> 5, lane = t & 31;
#pragma unroll
    for (int jj = 0; jj < 8; jj++) {
        int j = wid * 8 + jj;
        float v0 = A[lane][j], v1 = A[lane + 32][j];
        float m = fmaxf(v0, v1);
#pragma unroll
        for (int s = 16; s; s >>= 1) m = fmaxf(m, __shfl_xor_sync(0xffffffffu, m, s));
        float e0 = __expf(v0 - m), e1 = __expf(v1 - m);
        float sm = e0 + e1;
#pragma unroll
        for (int s = 16; s; s >>= 1) sm += __shfl_xor_sync(0xffffffffu, sm, s);
        float inv = 1.0f / sm;
        A[lane][j] = e0 * inv;
        A[lane + 32][j] = e1 * inv;
    }
    __syncthreads();
    {
        const int bH = b * NHH + H;
        const int ww = t >> 2, jj0 = (t & 3) * 16;
        __half* Cp = g_ChT + ((size_t)bH * NPIX + h * 64 + ww) * 64 + jj0;
        uint4 o[2];
        __half2* oh = (__half2*)o;
#pragma unroll
        for (int q = 0; q < 8; q++)
            oh[q] = __floats2half2_rn(A[jj0 + 2 * q][ww], A[jj0 + 2 * q + 1][ww]);
        *(uint4*)Cp = o[0];
        *(uint4*)(Cp + 8) = o[1];
    }
}

// ---------------- Kernel 4 (mma.sync fp16 + cp.async pipeline)
#define VROWB 144
#define STAGE_BYTES 4608

__global__ __launch_bounds__(256) void k_final(float* __restrict__ out) {
    __shared__ char smc[4 * STAGE_BYTES];
    float* Ds = (float*)smc;   // overlay after mainloop

    const int t = threadIdx.x, warp = t >> 5, lane = t & 31;
    const int p0 = blockIdx.x * 128;
    const int H = blockIdx.y, b = blockIdx.z;
    const int bH = b * NHH + H;
    const __half* Rh = g_Rh + (size_t)bH * 64 * NPIX + p0;
    const __half* Ct = g_ChT + ((size_t)bH * NPIX + p0) * 64;
    const __half* Vh = g_vh + (size_t)bH * 32 * NPIX;
    const float* Vg = g_p + ((size_t)(b * OC) + H * OPH + 4 * KD) * NPIX;

    const int prow = lane >> 2, qpair = lane & 3;
    const int pl = warp * 16 + prow;
    const int bl = lane & 15;
    const int brow = bl & 7, bk8 = (bl >> 3) * 8;
    const int vd = t >> 3, vc = (t & 7) * 8;

    u32 cf[4][4];
#pragma unroll
    for (int ks = 0; ks < 4; ks++) {
        int j0 = ks * 16 + qpair * 2;
        cf[ks][0] = *(const u32*)&Ct[(size_t)pl * 64 + j0];
        cf[ks][1] = *(const u32*)&Ct[(size_t)(pl + 8) * 64 + j0];
        cf[ks][2] = *(const u32*)&Ct[(size_t)pl * 64 + j0 + 8];
        cf[ks][3] = *(const u32*)&Ct[(size_t)(pl + 8) * 64 + j0 + 8];
    }

#define ISSUE_SLAB(s) do { \
    u32 dst = smem_u32(smc + ((s) & 3) * STAGE_BYTES + vd * VROWB + vc * 2); \
    const __half* src = Vh + (size_t)vd * NPIX + (s) * 64 + vc; \
    asm volatile("cp.async.cg.shared.global [%0], [%1], 16;" :: "r"(dst), "l"(src)); \
} while (0)
#define COMMIT() asm volatile("cp.async.commit_group;")

    ISSUE_SLAB(0); COMMIT();
    ISSUE_SLAB(1); COMMIT();
    ISSUE_SLAB(2); COMMIT();

    float acc[4][4] = {};

    for (int s = 0; s < 64; s++) {
        asm volatile("cp.async.wait_group 2;");
        __syncthreads();
        char* Vcur = smc + (s & 3) * STAGE_BYTES;
        __half2 rlo = __half2half2(Rh[(size_t)s * NPIX + pl]);
        __half2 rhi = __half2half2(Rh[(size_t)s * NPIX + pl + 8]);
#pragma unroll
        for (int ks = 0; ks < 4; ks++) {
            u32 a0 = h2u(__hmul2(rlo, *(__half2*)&cf[ks][0]));
            u32 a1 = h2u(__hmul2(rhi, *(__half2*)&cf[ks][1]));
            u32 a2 = h2u(__hmul2(rlo, *(__half2*)&cf[ks][2]));
            u32 a3 = h2u(__hmul2(rhi, *(__half2*)&cf[ks][3]));
#pragma unroll
            for (int nt = 0; nt < 4; nt++) {
                u32 baddr = smem_u32(Vcur + (nt * 8 + brow) * VROWB + (ks * 16 + bk8) * 2);
                u32 b0, b1;
                asm volatile("ldmatrix.sync.aligned.m8n8.x2.shared.b16 {%0,%1}, [%2];"
                             : "=r"(b0), "=r"(b1) : "r"(baddr));
                asm volatile(
                    "mma.sync.aligned.m16n8k16.row.col.f32.f16.f16.f32 "
                    "{%0,%1,%2,%3}, {%4,%5,%6,%7}, {%8,%9}, {%0,%1,%2,%3};"
                    : "+f"(acc[nt][0]), "+f"(acc[nt][1]),
                      "+f"(acc[nt][2]), "+f"(acc[nt][3])
                    : "r"(a0), "r"(a1), "r"(a2), "r"(a3), "r"(b0), "r"(b1));
            }
        }
        if (s + 3 < 64) ISSUE_SLAB(s + 3);
        COMMIT();
    }
    asm volatile("cp.async.wait_group 0;");
    __syncthreads();

#pragma unroll
    for (int nt = 0; nt < 4; nt++) {
        int d = nt * 8 + qpair * 2;
        Ds[d * 132 + pl]           = acc[nt][0];
        Ds[(d + 1) * 132 + pl]     = acc[nt][1];
        Ds[d * 132 + pl + 8]       = acc[nt][2];
        Ds[(d + 1) * 132 + pl + 8] = acc[nt][3];
    }
    __syncthreads();
#pragma unroll
    for (int u = 0; u < 4; u++) {
        int e = t + u * 256;
        int d = e >> 5, p4 = (e & 31) * 4;
        float4 r = *(const float4*)&Vg[(size_t)d * NPIX + p0 + p4];
        float4 v = *(const float4*)&Ds[d * 132 + p4];
        float4 o = {v.x + r.x, v.y + r.y, v.z + r.z, v.w + r.w};
        *(float4*)&out[((size_t)(b * 256) + H * 32 + d) * NPIX + p0 + p4] = o;
    }
}

extern "C" void kernel_launch(void* const* d_in, const int* in_sizes, int n_in,
                              void* d_out, int out_size) {
    const float* x = (const float*)d_in[0];
    const float* w = (const float*)d_in[1];
    if (n_in >= 2 && in_sizes[0] == OC * DIN) {
        const float* tmp = x; x = w; w = tmp;
    }
    float* out = (float*)d_out;

    k_prep_w<<<(OC * DIN / 2 + 255) / 256, 256>>>(w);
    k_prep_xt<<<dim3(128, 8, BB), 256>>>(x);
    k_projt<<<dim3(64, 10, BB), 256>>>();
    k_rowattn<<<dim3(64, NHH, BB), 256>>>();
    k_colattn<<<dim3(64, NHH, BB), 256>>>();
    k_final<<<dim3(32, NHH, BB), 256>>>(out);
}

// round 14
// speedup vs baseline: 1.6825x; 1.1682x over previous
#include <cuda_runtime.h>
#include <cuda_fp16.h>

#define NHH 8
#define KD 32
#define HD 32
#define OC 1280     // NH*(4*KD+HD)
#define DIN 256
#define NPIX 4096   // 64*64
#define BB 2
#define OPH 160     // channels per head
#define SCALE 0.17677669529663687f

typedef unsigned long long u64;
typedef unsigned int u32;

__device__ float g_p[BB * OC * NPIX];           // projection output [b][o][pix]
__device__ float g_qT[BB * NHH * 32 * NPIX];    // rq transposed [bH][d][w*64+i]
__device__ float g_kT[BB * NHH * 32 * NPIX];    // rk transposed [bH][d][w*64+i]
__device__ __half g_RhT[BB * NHH * NPIX * 64];  // row-attn weights fp16 p-major [bH][pix][i]
__device__ __half g_ChT[BB * NHH * NPIX * 64];  // col-attn weights fp16 p-major [bH][pix][j]
__device__ __half g_vh[BB * NHH * 32 * NPIX];   // V fp16 [bH][d][pix]
__device__ __half g_wh[OC * DIN];               // w hi fp16
__device__ __half g_wl[OC * DIN];               // w lo fp16 (residual)
__device__ __half g_xth[BB * NPIX * DIN];       // x^T hi fp16 [b][pix][c]
__device__ __half g_xtl[BB * NPIX * DIN];       // x^T lo fp16

__device__ __forceinline__ u32 smem_u32(const void* p) {
    u32 a;
    asm("{ .reg .u64 t; cvta.to.shared.u64 t, %1; cvt.u32.u64 %0, t; }" : "=r"(a) : "l"(p));
    return a;
}
__device__ __forceinline__ u32 h2u(__half2 h) { return *(u32*)&h; }

// ---------------- Prep A: w -> hi/lo fp16
__global__ __launch_bounds__(256) void k_prep_w(const float* __restrict__ w) {
    int gid = blockIdx.x * 256 + threadIdx.x;      // handles 2 elements
    if (gid * 2 >= OC * DIN) return;
    float2 v = *(const float2*)&w[gid * 2];
    __half h0 = __float2half_rn(v.x), h1 = __float2half_rn(v.y);
    __half l0 = __float2half_rn(v.x - __half2float(h0));
    __half l1 = __float2half_rn(v.y - __half2float(h1));
    ((__half2*)g_wh)[gid] = __halves2half2(h0, h1);
    ((__half2*)g_wl)[gid] = __halves2half2(l0, l1);
}

// ---------------- Prep B: x[c][pix] -> x^T[pix][c] hi/lo fp16 (32x32 smem transpose)
__global__ __launch_bounds__(256) void k_prep_xt(const float* __restrict__ x) {
    __shared__ float sx[32][33];
    const int b = blockIdx.z, c0 = blockIdx.y * 32, p0 = blockIdx.x * 32;
    const int t = threadIdx.x;
    const float* xb = x + (size_t)b * DIN * NPIX;
#pragma unroll
    for (int u = 0; u < 4; u++) {
        int ci = (t >> 5) + u * 8, pi = t & 31;
        sx[ci][pi] = xb[(size_t)(c0 + ci) * NPIX + p0 + pi];
    }
    __syncthreads();
#pragma unroll
    for (int u = 0; u < 4; u++) {
        int pi = (t >> 5) + u * 8, ci = t & 31;
        float v = sx[ci][pi];
        __half h = __float2half_rn(v);
        __half l = __float2half_rn(v - __half2float(h));
        size_t idx = ((size_t)b * NPIX + p0 + pi) * DIN + c0 + ci;
        g_xth[idx] = h;
        g_xtl[idx] = l;
    }
}

// ---------------- Kernel 1: projection via mma.sync fp16 3-way split (~fp32 accuracy)
__global__ __launch_bounds__(256) void k_projt() {
    __shared__ __half Ash[128 * 40], Asl[128 * 40];
    __shared__ __half Bsh[64 * 40], Bsl[64 * 40];
    const int b = blockIdx.z;
    const int m0 = blockIdx.y * 128;
    const int n0 = blockIdx.x * 64;
    const int t = threadIdx.x, warp = t >> 5, lane = t & 31;
    const int warp_m = warp >> 1, warp_n = warp & 1;
    const int obase = warp_m * 32, pbase = warp_n * 32;
    const int prow = lane >> 2, qp = lane & 3;
    const int arow = (lane & 7) + ((lane >> 3) & 1) * 8;
    const int acol = ((lane >> 4) & 1) * 8;
    const int bl = lane & 15;
    const int brow = bl & 7, bk8 = (bl >> 3) * 8;
    const int lar = t >> 1, lac = (t & 1) * 16;
    const int lbr = t >> 2, lbc = (t & 3) * 8;

    float acc[2][4][4] = {};

    for (int kc = 0; kc < 8; kc++) {
        const int k0 = kc * 32;
        if (kc) __syncthreads();
        {
            size_t wa = (size_t)(m0 + lar) * DIN + k0 + lac;
            *(uint4*)&Ash[lar * 40 + lac]     = *(const uint4*)&g_wh[wa];
            *(uint4*)&Ash[lar * 40 + lac + 8] = *(const uint4*)&g_wh[wa + 8];
            *(uint4*)&Asl[lar * 40 + lac]     = *(const uint4*)&g_wl[wa];
            *(uint4*)&Asl[lar * 40 + lac + 8] = *(const uint4*)&g_wl[wa + 8];
            size_t xa = ((size_t)b * NPIX + n0 + lbr) * DIN + k0 + lbc;
            *(uint4*)&Bsh[lbr * 40 + lbc] = *(const uint4*)&g_xth[xa];
            *(uint4*)&Bsl[lbr * 40 + lbc] = *(const uint4*)&g_xtl[xa];
        }
        __syncthreads();
#pragma unroll
        for (int kh = 0; kh < 2; kh++) {
            const int kk = kh * 16;
            u32 aH[2][4], aL[2][4], bH[4][2], bL[4][2];
#pragma unroll
            for (int mt = 0; mt < 2; mt++) {
                u32 aaddr = smem_u32(&Ash[(obase + mt * 16 + arow) * 40 + kk + acol]);
                asm volatile("ldmatrix.sync.aligned.m8n8.x4.shared.b16 {%0,%1,%2,%3}, [%4];"
                             : "=r"(aH[mt][0]), "=r"(aH[mt][1]), "=r"(aH[mt][2]), "=r"(aH[mt][3])
                             : "r"(aaddr));
                u32 aaddr2 = smem_u32(&Asl[(obase + mt * 16 + arow) * 40 + kk + acol]);
                asm volatile("ldmatrix.sync.aligned.m8n8.x4.shared.b16 {%0,%1,%2,%3}, [%4];"
                             : "=r"(aL[mt][0]), "=r"(aL[mt][1]), "=r"(aL[mt][2]), "=r"(aL[mt][3])
                             : "r"(aaddr2));
            }
#pragma unroll
            for (int nt = 0; nt < 4; nt++) {
                u32 baddr = smem_u32(&Bsh[(pbase + nt * 8 + brow) * 40 + kk + bk8]);
                asm volatile("ldmatrix.sync.aligned.m8n8.x2.shared.b16 {%0,%1}, [%2];"
                             : "=r"(bH[nt][0]), "=r"(bH[nt][1]) : "r"(baddr));
                u32 baddr2 = smem_u32(&Bsl[(pbase + nt * 8 + brow) * 40 + kk + bk8]);
                asm volatile("ldmatrix.sync.aligned.m8n8.x2.shared.b16 {%0,%1}, [%2];"
                             : "=r"(bL[nt][0]), "=r"(bL[nt][1]) : "r"(baddr2));
            }
#pragma unroll
            for (int mt = 0; mt < 2; mt++)
#pragma unroll
                for (int nt = 0; nt < 4; nt++) {
#define MMA(AF, BF) \
    asm volatile("mma.sync.aligned.m16n8k16.row.col.f32.f16.f16.f32 " \
                 "{%0,%1,%2,%3}, {%4,%5,%6,%7}, {%8,%9}, {%0,%1,%2,%3};" \
                 : "+f"(acc[mt][nt][0]), "+f"(acc[mt][nt][1]), \
                   "+f"(acc[mt][nt][2]), "+f"(acc[mt][nt][3]) \
                 : "r"(AF[mt][0]), "r"(AF[mt][1]), "r"(AF[mt][2]), "r"(AF[mt][3]), \
                   "r"(BF[nt][0]), "r"(BF[nt][1]))
                    MMA(aH, bH);
                    MMA(aH, bL);
                    MMA(aL, bH);
#undef MMA
                }
        }
    }
    float* pp = g_p + (size_t)b * OC * NPIX;
#pragma unroll
    for (int mt = 0; mt < 2; mt++) {
        int o = m0 + obase + mt * 16 + prow;
#pragma unroll
        for (int nt = 0; nt < 4; nt++) {
            int pix = n0 + pbase + nt * 8 + qp * 2;
            *(float2*)&pp[(size_t)o * NPIX + pix] =
                make_float2(acc[mt][nt][0], acc[mt][nt][1]);
            *(float2*)&pp[(size_t)(o + 8) * NPIX + pix] =
                make_float2(acc[mt][nt][2], acc[mt][nt][3]);
        }
        // fused fp16 V emit (channels o%OPH in [128,160))
#pragma unroll
        for (int half_off = 0; half_off < 2; half_off++) {
            int oo = o + half_off * 8;
            int Hh = oo / OPH, c = oo % OPH;
            if (c >= 4 * KD) {
                int d = c - 4 * KD;
                __half* vdst = g_vh + ((size_t)(b * NHH + Hh) * 32 + d) * NPIX;
#pragma unroll
                for (int nt = 0; nt < 4; nt++) {
                    int pix = n0 + pbase + nt * 8 + qp * 2;
                    *(__half2*)&vdst[pix] =
                        __floats2half2_rn(acc[mt][nt][half_off * 2],
                                          acc[mt][nt][half_off * 2 + 1]);
                }
            }
        }
    }
}

// ---------------- Transpose rq/rk pixel grids: [d][i*64+w] -> [d][w*64+i]
// Block per (b,H,c) with c in [0,64): c<32 -> rq plane d=c; else rk plane d=c-32.
__global__ __launch_bounds__(256) void k_qkT() {
    __shared__ float s[64][65];
    const int c = blockIdx.x, H = blockIdx.y, b = blockIdx.z;
    const int t = threadIdx.x;
    const int d = c & 31;
    const float* src = g_p + ((size_t)(b * OC) + H * OPH + (c >> 5) * KD + d) * NPIX;
    float* dst = ((c >> 5) ? g_kT : g_qT) + ((size_t)(b * NHH + H) * 32 + d) * NPIX;
#pragma unroll
    for (int u = 0; u < 16; u++) {
        int idx = t + u * 256;
        s[idx >> 6][idx & 63] = src[idx];
    }
    __syncthreads();
#pragma unroll
    for (int u = 0; u < 16; u++) {
        int idx = t + u * 256;        // idx = w*64 + i
        dst[idx] = s[idx & 63][idx >> 6];
    }
}

// ---------------- Kernel 2: row attention.  Block per (b,H,w).
// Coalesced loads from g_qT/g_kT; writes p-major fp16 R^T.
__global__ __launch_bounds__(256) void k_rowattn() {
    __shared__ float sq[32][64];
    __shared__ float sk[32][64];
    __shared__ float A[64][65];
    const int w = blockIdx.x, H = blockIdx.y, b = blockIdx.z;
    const int t = threadIdx.x;
    const int bH = b * NHH + H;
    const float* pq = g_qT + (size_t)bH * 32 * NPIX + w * 64;
    const float* pk = g_kT + (size_t)bH * 32 * NPIX + w * 64;
#pragma unroll
    for (int u = 0; u < 2; u++) {
        int e = t + u * 256;
        int d = e >> 4, i4 = (e & 15) * 4;
        *(float4*)&sq[d][i4] = *(const float4*)&pq[(size_t)d * NPIX + i4];
        *(float4*)&sk[d][i4] = *(const float4*)&pk[(size_t)d * NPIX + i4];
    }
    __syncthreads();
    {
        const int ti = (t >> 4) * 4, tj = (t & 15) * 4;
        float acc[4][4] = {};
#pragma unroll 8
        for (int d = 0; d < 32; d++) {
            float4 av = *(const float4*)&sq[d][ti];
            float4 bv = *(const float4*)&sk[d][tj];
            float a[4] = {av.x, av.y, av.z, av.w};
            float bb2[4] = {bv.x, bv.y, bv.z, bv.w};
#pragma unroll
            for (int ii = 0; ii < 4; ii++)
#pragma unroll
                for (int jj = 0; jj < 4; jj++)
                    acc[ii][jj] = fmaf(a[ii], bb2[jj], acc[ii][jj]);
        }
#pragma unroll
        for (int ii = 0; ii < 4; ii++)
#pragma unroll
            for (int jj = 0; jj < 4; jj++)
                A[ti + ii][tj + jj] = acc[ii][jj] * SCALE;
    }
    __syncthreads();
    const int wid = t >> 5, lane = t & 31;
#pragma unroll
    for (int jj = 0; jj < 8; jj++) {
        int j = wid * 8 + jj;
        float v0 = A[lane][j], v1 = A[lane + 32][j];
        float m = fmaxf(v0, v1);
#pragma unroll
        for (int s = 16; s; s >>= 1) m = fmaxf(m, __shfl_xor_sync(0xffffffffu, m, s));
        float e0 = __expf(v0 - m), e1 = __expf(v1 - m);
        float sm = e0 + e1;
#pragma unroll
        for (int s = 16; s; s >>= 1) sm += __shfl_xor_sync(0xffffffffu, sm, s);
        float inv = 1.0f / sm;
        A[lane][j] = e0 * inv;
        A[lane + 32][j] = e1 * inv;
    }
    __syncthreads();
    // Coalesced p-major write: g_RhT[bH][j*64+w][i] (128B rows)
    {
        const int j = t >> 2, seg = (t & 3) * 16;
        __half* Rp = g_RhT + ((size_t)bH * NPIX + j * 64 + w) * 64 + seg;
        uint4 o[2];
        __half2* oh = (__half2*)o;
#pragma unroll
        for (int q = 0; q < 8; q++)
            oh[q] = __floats2half2_rn(A[seg + 2 * q][j], A[seg + 2 * q + 1][j]);
        *(uint4*)Rp = o[0];
        *(uint4*)(Rp + 8) = o[1];
    }
}

// ---------------- Kernel 3: column attention.  Block per (b,H,h).  Writes fp16 C^T (p-major).
__global__ __launch_bounds__(256) void k_colattn() {
    __shared__ float sq[32][64];
    __shared__ float sk[32][64];
    __shared__ float A[64][65];
    const int h = blockIdx.x, H = blockIdx.y, b = blockIdx.z;
    const int t = threadIdx.x;
    const float* pq = g_p + ((size_t)(b * OC) + H * OPH + 2 * KD) * NPIX + h * 64;
    const float* pk = g_p + ((size_t)(b * OC) + H * OPH + 3 * KD) * NPIX + h * 64;
#pragma unroll
    for (int u = 0; u < 2; u++) {
        int e = t + u * 256;
        int d = e >> 4, c4 = (e & 15) * 4;
        *(float4*)&sq[d][c4] = *(const float4*)&pq[(size_t)d * NPIX + c4];
        *(float4*)&sk[d][c4] = *(const float4*)&pk[(size_t)d * NPIX + c4];
    }
    __syncthreads();
    {
        const int ti = (t >> 4) * 4, tj = (t & 15) * 4;
        float acc[4][4] = {};
#pragma unroll 8
        for (int d = 0; d < 32; d++) {
            float4 av = *(const float4*)&sq[d][ti];
            float4 bv = *(const float4*)&sk[d][tj];
            float a[4] = {av.x, av.y, av.z, av.w};
            float bb2[4] = {bv.x, bv.y, bv.z, bv.w};
#pragma unroll
            for (int ii = 0; ii < 4; ii++)
#pragma unroll
                for (int jj = 0; jj < 4; jj++)
                    acc[ii][jj] = fmaf(a[ii], bb2[jj], acc[ii][jj]);
        }
#pragma unroll
        for (int ii = 0; ii < 4; ii++)
#pragma unroll
            for (int jj = 0; jj < 4; jj++)
                A[ti + ii][tj + jj] = acc[ii][jj] * SCALE;
    }
    __syncthreads();
    const int wid = t >> 5, lane = t & 31;
#pragma unroll
    for (int jj = 0; jj < 8; jj++) {
        int j = wid * 8 + jj;
        float v0 = A[lane][j], v1 = A[lane + 32][j];
        float m = fmaxf(v0, v1);
#pragma unroll
        for (int s = 16; s; s >>= 1) m = fmaxf(m, __shfl_xor_sync(0xffffffffu, m, s));
        float e0 = __expf(v0 - m), e1 = __expf(v1 - m);
        float sm = e0 + e1;
#pragma unroll
        for (int s = 16; s; s >>= 1) sm += __shfl_xor_sync(0xffffffffu, sm, s);
        float inv = 1.0f / sm;
        A[lane][j] = e0 * inv;
        A[lane + 32][j] = e1 * inv;
    }
    __syncthreads();
    {
        const int bH = b * NHH + H;
        const int ww = t >> 2, jj0 = (t & 3) * 16;
        __half* Cp = g_ChT + ((size_t)bH * NPIX + h * 64 + ww) * 64 + jj0;
        uint4 o[2];
        __half2* oh = (__half2*)o;
#pragma unroll
        for (int q = 0; q < 8; q++)
            oh[q] = __floats2half2_rn(A[jj0 + 2 * q][ww], A[jj0 + 2 * q + 1][ww]);
        *(uint4*)Cp = o[0];
        *(uint4*)(Cp + 8) = o[1];
    }
}

// ---------------- Kernel 4 (mma.sync fp16 + cp.async pipeline)
#define VROWB 144
#define STAGE_BYTES 4608

__global__ __launch_bounds__(256) void k_final(float* __restrict__ out) {
    __shared__ char smc[4 * STAGE_BYTES];
    float* Ds = (float*)smc;   // overlay after mainloop

    const int t = threadIdx.x, warp = t >> 5, lane = t & 31;
    const int p0 = blockIdx.x * 128;
    const int H = blockIdx.y, b = blockIdx.z;
    const int bH = b * NHH + H;
    const __half* Rt = g_RhT + ((size_t)bH * NPIX + p0) * 64;
    const __half* Ct = g_ChT + ((size_t)bH * NPIX + p0) * 64;
    const __half* Vh = g_vh + (size_t)bH * 32 * NPIX;
    const float* Vg = g_p + ((size_t)(b * OC) + H * OPH + 4 * KD) * NPIX;

    const int prow = lane >> 2, qpair = lane & 3;
    const int pl = warp * 16 + prow;
    const int bl = lane & 15;
    const int brow = bl & 7, bk8 = (bl >> 3) * 8;
    const int vd = t >> 3, vc = (t & 7) * 8;

    u32 cf[4][4];
#pragma unroll
    for (int ks = 0; ks < 4; ks++) {
        int j0 = ks * 16 + qpair * 2;
        cf[ks][0] = *(const u32*)&Ct[(size_t)pl * 64 + j0];
        cf[ks][1] = *(const u32*)&Ct[(size_t)(pl + 8) * 64 + j0];
        cf[ks][2] = *(const u32*)&Ct[(size_t)pl * 64 + j0 + 8];
        cf[ks][3] = *(const u32*)&Ct[(size_t)(pl + 8) * 64 + j0 + 8];
    }

#define ISSUE_SLAB(s) do { \
    u32 dst = smem_u32(smc + ((s) & 3) * STAGE_BYTES + vd * VROWB + vc * 2); \
    const __half* src = Vh + (size_t)vd * NPIX + (s) * 64 + vc; \
    asm volatile("cp.async.cg.shared.global [%0], [%1], 16;" :: "r"(dst), "l"(src)); \
} while (0)
#define COMMIT() asm volatile("cp.async.commit_group;")

    ISSUE_SLAB(0); COMMIT();
    ISSUE_SLAB(1); COMMIT();
    ISSUE_SLAB(2); COMMIT();

    float acc[4][4] = {};

    for (int s = 0; s < 64; s++) {
        asm volatile("cp.async.wait_group 2;");
        __syncthreads();
        char* Vcur = smc + (s & 3) * STAGE_BYTES;
        __half2 rlo = __half2half2(Rt[(size_t)pl * 64 + s]);
        __half2 rhi = __half2half2(Rt[(size_t)(pl + 8) * 64 + s]);
#pragma unroll
        for (int ks = 0; ks < 4; ks++) {
            u32 a0 = h2u(__hmul2(rlo, *(__half2*)&cf[ks][0]));
            u32 a1 = h2u(__hmul2(rhi, *(__half2*)&cf[ks][1]));
            u32 a2 = h2u(__hmul2(rlo, *(__half2*)&cf[ks][2]));
            u32 a3 = h2u(__hmul2(rhi, *(__half2*)&cf[ks][3]));
#pragma unroll
            for (int nt = 0; nt < 4; nt++) {
                u32 baddr = smem_u32(Vcur + (nt * 8 + brow) * VROWB + (ks * 16 + bk8) * 2);
                u32 b0, b1;
                asm volatile("ldmatrix.sync.aligned.m8n8.x2.shared.b16 {%0,%1}, [%2];"
                             : "=r"(b0), "=r"(b1) : "r"(baddr));
                asm volatile(
                    "mma.sync.aligned.m16n8k16.row.col.f32.f16.f16.f32 "
                    "{%0,%1,%2,%3}, {%4,%5,%6,%7}, {%8,%9}, {%0,%1,%2,%3};"
                    : "+f"(acc[nt][0]), "+f"(acc[nt][1]),
                      "+f"(acc[nt][2]), "+f"(acc[nt][3])
                    : "r"(a0), "r"(a1), "r"(a2), "r"(a3), "r"(b0), "r"(b1));
            }
        }
        if (s + 3 < 64) ISSUE_SLAB(s + 3);
        COMMIT();
    }
    asm volatile("cp.async.wait_group 0;");
    __syncthreads();

#pragma unroll
    for (int nt = 0; nt < 4; nt++) {
        int d = nt * 8 + qpair * 2;
        Ds[d * 132 + pl]           = acc[nt][0];
        Ds[(d + 1) * 132 + pl]     = acc[nt][1];
        Ds[d * 132 + pl + 8]       = acc[nt][2];
        Ds[(d + 1) * 132 + pl + 8] = acc[nt][3];
    }
    __syncthreads();
#pragma unroll
    for (int u = 0; u < 4; u++) {
        int e = t + u * 256;
        int d = e >> 5, p4 = (e & 31) * 4;
        float4 r = *(const float4*)&Vg[(size_t)d * NPIX + p0 + p4];
        float4 v = *(const float4*)&Ds[d * 132 + p4];
        float4 o = {v.x + r.x, v.y + r.y, v.z + r.z, v.w + r.w};
        *(float4*)&out[((size_t)(b * 256) + H * 32 + d) * NPIX + p0 + p4] = o;
    }
}

extern "C" void kernel_launch(void* const* d_in, const int* in_sizes, int n_in,
                              void* d_out, int out_size) {
    const float* x = (const float*)d_in[0];
    const float* w = (const float*)d_in[1];
    if (n_in >= 2 && in_sizes[0] == OC * DIN) {
        const float* tmp = x; x = w; w = tmp;
    }
    float* out = (float*)d_out;

    k_prep_w<<<(OC * DIN / 2 + 255) / 256, 256>>>(w);
    k_prep_xt<<<dim3(128, 8, BB), 256>>>(x);
    k_projt<<<dim3(64, 10, BB), 256>>>();
    k_qkT<<<dim3(64, NHH, BB), 256>>>();
    k_rowattn<<<dim3(64, NHH, BB), 256>>>();
    k_colattn<<<dim3(64, NHH, BB), 256>>>();
    k_final<<<dim3(32, NHH, BB), 256>>>(out);
}

// round 16
// speedup vs baseline: 1.8301x; 1.0877x over previous
#include <cuda_runtime.h>
#include <cuda_fp16.h>

#define NHH 8
#define KD 32
#define HD 32
#define OC 1280     // NH*(4*KD+HD)
#define DIN 256
#define NPIX 4096   // 64*64
#define BB 2
#define OPH 160     // channels per head
#define SCALE 0.17677669529663687f

typedef unsigned long long u64;
typedef unsigned int u32;

__device__ float g_p[BB * OC * NPIX];           // projection output [b][o][pix]
__device__ float g_qT[BB * NHH * 32 * NPIX];    // rq transposed [bH][d][w*64+i]
__device__ float g_kT[BB * NHH * 32 * NPIX];    // rk transposed [bH][d][w*64+i]
__device__ __half g_RhT[BB * NHH * NPIX * 64];  // row-attn weights fp16 p-major [bH][pix][i]
__device__ __half g_ChT[BB * NHH * NPIX * 64];  // col-attn weights fp16 p-major [bH][pix][j]
__device__ __half g_vh[BB * NHH * 32 * NPIX];   // V fp16 [bH][d][pix]
__device__ __half g_wh[OC * DIN];               // w hi fp16
__device__ __half g_wl[OC * DIN];               // w lo fp16 (residual)
__device__ __half g_xth[BB * NPIX * DIN];       // x^T hi fp16 [b][pix][c]
__device__ __half g_xtl[BB * NPIX * DIN];       // x^T lo fp16

__device__ __forceinline__ u32 smem_u32(const void* p) {
    u32 a;
    asm("{ .reg .u64 t; cvta.to.shared.u64 t, %1; cvt.u32.u64 %0, t; }" : "=r"(a) : "l"(p));
    return a;
}
__device__ __forceinline__ u32 h2u(__half2 h) { return *(u32*)&h; }

// ---------------- Prep A: w -> hi/lo fp16
__global__ __launch_bounds__(256) void k_prep_w(const float* __restrict__ w) {
    int gid = blockIdx.x * 256 + threadIdx.x;      // handles 2 elements
    if (gid * 2 >= OC * DIN) return;
    float2 v = *(const float2*)&w[gid * 2];
    __half h0 = __float2half_rn(v.x), h1 = __float2half_rn(v.y);
    __half l0 = __float2half_rn(v.x - __half2float(h0));
    __half l1 = __float2half_rn(v.y - __half2float(h1));
    ((__half2*)g_wh)[gid] = __halves2half2(h0, h1);
    ((__half2*)g_wl)[gid] = __halves2half2(l0, l1);
}

// ---------------- Prep B: x[c][pix] -> x^T[pix][c] hi/lo fp16 (32x32 smem transpose)
__global__ __launch_bounds__(256) void k_prep_xt(const float* __restrict__ x) {
    __shared__ float sx[32][33];
    const int b = blockIdx.z, c0 = blockIdx.y * 32, p0 = blockIdx.x * 32;
    const int t = threadIdx.x;
    const float* xb = x + (size_t)b * DIN * NPIX;
#pragma unroll
    for (int u = 0; u < 4; u++) {
        int ci = (t >> 5) + u * 8, pi = t & 31;
        sx[ci][pi] = xb[(size_t)(c0 + ci) * NPIX + p0 + pi];
    }
    __syncthreads();
#pragma unroll
    for (int u = 0; u < 4; u++) {
        int pi = (t >> 5) + u * 8, ci = t & 31;
        float v = sx[ci][pi];
        __half h = __float2half_rn(v);
        __half l = __float2half_rn(v - __half2float(h));
        size_t idx = ((size_t)b * NPIX + p0 + pi) * DIN + c0 + ci;
        g_xth[idx] = h;
        g_xtl[idx] = l;
    }
}

// ---------------- Kernel 1: projection via mma.sync fp16 3-way split (~fp32 accuracy)
__global__ __launch_bounds__(256) void k_projt() {
    __shared__ __half Ash[128 * 40], Asl[128 * 40];
    __shared__ __half Bsh[64 * 40], Bsl[64 * 40];
    const int b = blockIdx.z;
    const int m0 = blockIdx.y * 128;
    const int n0 = blockIdx.x * 64;
    const int t = threadIdx.x, warp = t >> 5, lane = t & 31;
    const int warp_m = warp >> 1, warp_n = warp & 1;
    const int obase = warp_m * 32, pbase = warp_n * 32;
    const int prow = lane >> 2, qp = lane & 3;
    const int arow = (lane & 7) + ((lane >> 3) & 1) * 8;
    const int acol = ((lane >> 4) & 1) * 8;
    const int bl = lane & 15;
    const int brow = bl & 7, bk8 = (bl >> 3) * 8;
    const int lar = t >> 1, lac = (t & 1) * 16;
    const int lbr = t >> 2, lbc = (t & 3) * 8;

    float acc[2][4][4] = {};

    for (int kc = 0; kc < 8; kc++) {
        const int k0 = kc * 32;
        if (kc) __syncthreads();
        {
            size_t wa = (size_t)(m0 + lar) * DIN + k0 + lac;
            *(uint4*)&Ash[lar * 40 + lac]     = *(const uint4*)&g_wh[wa];
            *(uint4*)&Ash[lar * 40 + lac + 8] = *(const uint4*)&g_wh[wa + 8];
            *(uint4*)&Asl[lar * 40 + lac]     = *(const uint4*)&g_wl[wa];
            *(uint4*)&Asl[lar * 40 + lac + 8] = *(const uint4*)&g_wl[wa + 8];
            size_t xa = ((size_t)b * NPIX + n0 + lbr) * DIN + k0 + lbc;
            *(uint4*)&Bsh[lbr * 40 + lbc] = *(const uint4*)&g_xth[xa];
            *(uint4*)&Bsl[lbr * 40 + lbc] = *(const uint4*)&g_xtl[xa];
        }
        __syncthreads();
#pragma unroll
        for (int kh = 0; kh < 2; kh++) {
            const int kk = kh * 16;
            u32 aH[2][4], aL[2][4], bH[4][2], bL[4][2];
#pragma unroll
            for (int mt = 0; mt < 2; mt++) {
                u32 aaddr = smem_u32(&Ash[(obase + mt * 16 + arow) * 40 + kk + acol]);
                asm volatile("ldmatrix.sync.aligned.m8n8.x4.shared.b16 {%0,%1,%2,%3}, [%4];"
                             : "=r"(aH[mt][0]), "=r"(aH[mt][1]), "=r"(aH[mt][2]), "=r"(aH[mt][3])
                             : "r"(aaddr));
                u32 aaddr2 = smem_u32(&Asl[(obase + mt * 16 + arow) * 40 + kk + acol]);
                asm volatile("ldmatrix.sync.aligned.m8n8.x4.shared.b16 {%0,%1,%2,%3}, [%4];"
                             : "=r"(aL[mt][0]), "=r"(aL[mt][1]), "=r"(aL[mt][2]), "=r"(aL[mt][3])
                             : "r"(aaddr2));
            }
#pragma unroll
            for (int nt = 0; nt < 4; nt++) {
                u32 baddr = smem_u32(&Bsh[(pbase + nt * 8 + brow) * 40 + kk + bk8]);
                asm volatile("ldmatrix.sync.aligned.m8n8.x2.shared.b16 {%0,%1}, [%2];"
                             : "=r"(bH[nt][0]), "=r"(bH[nt][1]) : "r"(baddr));
                u32 baddr2 = smem_u32(&Bsl[(pbase + nt * 8 + brow) * 40 + kk + bk8]);
                asm volatile("ldmatrix.sync.aligned.m8n8.x2.shared.b16 {%0,%1}, [%2];"
                             : "=r"(bL[nt][0]), "=r"(bL[nt][1]) : "r"(baddr2));
            }
#pragma unroll
            for (int mt = 0; mt < 2; mt++)
#pragma unroll
                for (int nt = 0; nt < 4; nt++) {
#define MMA(AF, BF) \
    asm volatile("mma.sync.aligned.m16n8k16.row.col.f32.f16.f16.f32 " \
                 "{%0,%1,%2,%3}, {%4,%5,%6,%7}, {%8,%9}, {%0,%1,%2,%3};" \
                 : "+f"(acc[mt][nt][0]), "+f"(acc[mt][nt][1]), \
                   "+f"(acc[mt][nt][2]), "+f"(acc[mt][nt][3]) \
                 : "r"(AF[mt][0]), "r"(AF[mt][1]), "r"(AF[mt][2]), "r"(AF[mt][3]), \
                   "r"(BF[nt][0]), "r"(BF[nt][1]))
                    MMA(aH, bH);
                    MMA(aH, bL);
                    MMA(aL, bH);
#undef MMA
                }
        }
    }
    float* pp = g_p + (size_t)b * OC * NPIX;
#pragma unroll
    for (int mt = 0; mt < 2; mt++) {
        int o = m0 + obase + mt * 16 + prow;
#pragma unroll
        for (int nt = 0; nt < 4; nt++) {
            int pix = n0 + pbase + nt * 8 + qp * 2;
            *(float2*)&pp[(size_t)o * NPIX + pix] =
                make_float2(acc[mt][nt][0], acc[mt][nt][1]);
            *(float2*)&pp[(size_t)(o + 8) * NPIX + pix] =
                make_float2(acc[mt][nt][2], acc[mt][nt][3]);
        }
        // fused fp16 V emit (channels o%OPH in [128,160))
#pragma unroll
        for (int half_off = 0; half_off < 2; half_off++) {
            int oo = o + half_off * 8;
            int Hh = oo / OPH, c = oo % OPH;
            if (c >= 4 * KD) {
                int d = c - 4 * KD;
                __half* vdst = g_vh + ((size_t)(b * NHH + Hh) * 32 + d) * NPIX;
#pragma unroll
                for (int nt = 0; nt < 4; nt++) {
                    int pix = n0 + pbase + nt * 8 + qp * 2;
                    *(__half2*)&vdst[pix] =
                        __floats2half2_rn(acc[mt][nt][half_off * 2],
                                          acc[mt][nt][half_off * 2 + 1]);
                }
            }
        }
    }
}

// ---------------- Transpose rq/rk pixel grids: [d][i*64+w] -> [d][w*64+i]
__global__ __launch_bounds__(256) void k_qkT() {
    __shared__ float s[64][65];
    const int c = blockIdx.x, H = blockIdx.y, b = blockIdx.z;
    const int t = threadIdx.x;
    const int d = c & 31;
    const float* src = g_p + ((size_t)(b * OC) + H * OPH + (c >> 5) * KD + d) * NPIX;
    float* dst = ((c >> 5) ? g_kT : g_qT) + ((size_t)(b * NHH + H) * 32 + d) * NPIX;
#pragma unroll
    for (int u = 0; u < 16; u++) {
        int idx = t + u * 256;
        s[idx >> 6][idx & 63] = src[idx];
    }
    __syncthreads();
#pragma unroll
    for (int u = 0; u < 16; u++) {
        int idx = t + u * 256;        // idx = w*64 + i
        dst[idx] = s[idx & 63][idx >> 6];
    }
}

// ---------------- Kernel 2: row attention.  Block per (b,H,w).
__global__ __launch_bounds__(256) void k_rowattn() {
    __shared__ float sq[32][64];
    __shared__ float sk[32][64];
    __shared__ float A[64][65];
    const int w = blockIdx.x, H = blockIdx.y, b = blockIdx.z;
    const int t = threadIdx.x;
    const int bH = b * NHH + H;
    const float* pq = g_qT + (size_t)bH * 32 * NPIX + w * 64;
    const float* pk = g_kT + (size_t)bH * 32 * NPIX + w * 64;
#pragma unroll
    for (int u = 0; u < 2; u++) {
        int e = t + u * 256;
        int d = e >> 4, i4 = (e & 15) * 4;
        *(float4*)&sq[d][i4] = *(const float4*)&pq[(size_t)d * NPIX + i4];
        *(float4*)&sk[d][i4] = *(const float4*)&pk[(size_t)d * NPIX + i4];
    }
    __syncthreads();
    {
        const int ti = (t >> 4) * 4, tj = (t & 15) * 4;
        float acc[4][4] = {};
#pragma unroll 8
        for (int d = 0; d < 32; d++) {
            float4 av = *(const float4*)&sq[d][ti];
            float4 bv = *(const float4*)&sk[d][tj];
            float a[4] = {av.x, av.y, av.z, av.w};
            float bb2[4] = {bv.x, bv.y, bv.z, bv.w};
#pragma unroll
            for (int ii = 0; ii < 4; ii++)
#pragma unroll
                for (int jj = 0; jj < 4; jj++)
                    acc[ii][jj] = fmaf(a[ii], bb2[jj], acc[ii][jj]);
        }
#pragma unroll
        for (int ii = 0; ii < 4; ii++)
#pragma unroll
            for (int jj = 0; jj < 4; jj++)
                A[ti + ii][tj + jj] = acc[ii][jj] * SCALE;
    }
    __syncthreads();
    const int wid = t >> 5, lane = t & 31;
#pragma unroll
    for (int jj = 0; jj < 8; jj++) {
        int j = wid * 8 + jj;
        float v0 = A[lane][j], v1 = A[lane + 32][j];
        float m = fmaxf(v0, v1);
#pragma unroll
        for (int s = 16; s; s >>= 1) m = fmaxf(m, __shfl_xor_sync(0xffffffffu, m, s));
        float e0 = __expf(v0 - m), e1 = __expf(v1 - m);
        float sm = e0 + e1;
#pragma unroll
        for (int s = 16; s; s >>= 1) sm += __shfl_xor_sync(0xffffffffu, sm, s);
        float inv = 1.0f / sm;
        A[lane][j] = e0 * inv;
        A[lane + 32][j] = e1 * inv;
    }
    __syncthreads();
    {
        const int j = t >> 2, seg = (t & 3) * 16;
        __half* Rp = g_RhT + ((size_t)bH * NPIX + j * 64 + w) * 64 + seg;
        uint4 o[2];
        __half2* oh = (__half2*)o;
#pragma unroll
        for (int q = 0; q < 8; q++)
            oh[q] = __floats2half2_rn(A[seg + 2 * q][j], A[seg + 2 * q + 1][j]);
        *(uint4*)Rp = o[0];
        *(uint4*)(Rp + 8) = o[1];
    }
}

// ---------------- Kernel 3: column attention.  Block per (b,H,h).  Writes fp16 C^T (p-major).
__global__ __launch_bounds__(256) void k_colattn() {
    __shared__ float sq[32][64];
    __shared__ float sk[32][64];
    __shared__ float A[64][65];
    const int h = blockIdx.x, H = blockIdx.y, b = blockIdx.z;
    const int t = threadIdx.x;
    const float* pq = g_p + ((size_t)(b * OC) + H * OPH + 2 * KD) * NPIX + h * 64;
    const float* pk = g_p + ((size_t)(b * OC) + H * OPH + 3 * KD) * NPIX + h * 64;
#pragma unroll
    for (int u = 0; u < 2; u++) {
        int e = t + u * 256;
        int d = e >> 4, c4 = (e & 15) * 4;
        *(float4*)&sq[d][c4] = *(const float4*)&pq[(size_t)d * NPIX + c4];
        *(float4*)&sk[d][c4] = *(const float4*)&pk[(size_t)d * NPIX + c4];
    }
    __syncthreads();
    {
        const int ti = (t >> 4) * 4, tj = (t & 15) * 4;
        float acc[4][4] = {};
#pragma unroll 8
        for (int d = 0; d < 32; d++) {
            float4 av = *(const float4*)&sq[d][ti];
            float4 bv = *(const float4*)&sk[d][tj];
            float a[4] = {av.x, av.y, av.z, av.w};
            float bb2[4] = {bv.x, bv.y, bv.z, bv.w};
#pragma unroll
            for (int ii = 0; ii < 4; ii++)
#pragma unroll
                for (int jj = 0; jj < 4; jj++)
                    acc[ii][jj] = fmaf(a[ii], bb2[jj], acc[ii][jj]);
        }
#pragma unroll
        for (int ii = 0; ii < 4; ii++)
#pragma unroll
            for (int jj = 0; jj < 4; jj++)
                A[ti + ii][tj + jj] = acc[ii][jj] * SCALE;
    }
    __syncthreads();
    const int wid = t >> 5, lane = t & 31;
#pragma unroll
    for (int jj = 0; jj < 8; jj++) {
        int j = wid * 8 + jj;
        float v0 = A[lane][j], v1 = A[lane + 32][j];
        float m = fmaxf(v0, v1);
#pragma unroll
        for (int s = 16; s; s >>= 1) m = fmaxf(m, __shfl_xor_sync(0xffffffffu, m, s));
        float e0 = __expf(v0 - m), e1 = __expf(v1 - m);
        float sm = e0 + e1;
#pragma unroll
        for (int s = 16; s; s >>= 1) sm += __shfl_xor_sync(0xffffffffu, sm, s);
        float inv = 1.0f / sm;
        A[lane][j] = e0 * inv;
        A[lane + 32][j] = e1 * inv;
    }
    __syncthreads();
    {
        const int bH = b * NHH + H;
        const int ww = t >> 2, jj0 = (t & 3) * 16;
        __half* Cp = g_ChT + ((size_t)bH * NPIX + h * 64 + ww) * 64 + jj0;
        uint4 o[2];
        __half2* oh = (__half2*)o;
#pragma unroll
        for (int q = 0; q < 8; q++)
            oh[q] = __floats2half2_rn(A[jj0 + 2 * q][ww], A[jj0 + 2 * q + 1][ww]);
        *(uint4*)Cp = o[0];
        *(uint4*)(Cp + 8) = o[1];
    }
}

// ---------------- Kernel 4 (mma.sync fp16, 2-slab stages, x4 ldmatrix)
#define VROWB 144
#define SLAB_BYTES 4608                // 32 rows x 144B
#define STG_BYTES (2 * SLAB_BYTES)     // 2 slabs per stage
#define NSTG 3

__global__ __launch_bounds__(256) void k_final(float* __restrict__ out) {
    __shared__ char smc[NSTG * STG_BYTES];   // 27648 B
    float* Ds = (float*)smc;   // overlay after mainloop (needs 16896 B)

    const int t = threadIdx.x, warp = t >> 5, lane = t & 31;
    const int p0 = blockIdx.x * 128;
    const int H = blockIdx.y, b = blockIdx.z;
    const int bH = b * NHH + H;
    const __half* Rt = g_RhT + ((size_t)bH * NPIX + p0) * 64;
    const __half* Ct = g_ChT + ((size_t)bH * NPIX + p0) * 64;
    const __half* Vh = g_vh + (size_t)bH * 32 * NPIX;
    const float* Vg = g_p + ((size_t)(b * OC) + H * OPH + 4 * KD) * NPIX;

    const int prow = lane >> 2, qpair = lane & 3;
    const int pl = warp * 16 + prow;
    // x4 ldmatrix lane mapping: matrix id = lane>>3 (ntA-klo, ntA-khi, ntB-klo, ntB-khi)
    const int xm = lane >> 3, xr = lane & 7;
    const int xoff = ((xm >> 1) * 8 + xr) * VROWB + (xm & 1) * 16;  // byte offset in slab
    const int vd = t >> 3, vc = (t & 7) * 8;

    // C-fragments: invariant across all 64 slabs
    u32 cf[4][4];
#pragma unroll
    for (int ks = 0; ks < 4; ks++) {
        int j0 = ks * 16 + qpair * 2;
        cf[ks][0] = *(const u32*)&Ct[(size_t)pl * 64 + j0];
        cf[ks][1] = *(const u32*)&Ct[(size_t)(pl + 8) * 64 + j0];
        cf[ks][2] = *(const u32*)&Ct[(size_t)pl * 64 + j0 + 8];
        cf[ks][3] = *(const u32*)&Ct[(size_t)(pl + 8) * 64 + j0 + 8];
    }

#define ISSUE_STAGE(ss) do { \
    u32 dst0 = smem_u32(smc + ((ss) % NSTG) * STG_BYTES + vd * VROWB + vc * 2); \
    const __half* src0 = Vh + (size_t)vd * NPIX + (2 * (ss)) * 64 + vc; \
    asm volatile("cp.async.cg.shared.global [%0], [%1], 16;" :: "r"(dst0), "l"(src0)); \
    asm volatile("cp.async.cg.shared.global [%0], [%1], 16;" \
                 :: "r"(dst0 + SLAB_BYTES), "l"(src0 + 64)); \
} while (0)
#define COMMIT() asm volatile("cp.async.commit_group;")

    ISSUE_STAGE(0); COMMIT();
    ISSUE_STAGE(1); COMMIT();

    float acc[4][4] = {};

    for (int ss = 0; ss < 32; ss++) {
        asm volatile("cp.async.wait_group 1;");
        __syncthreads();
        const char* Vstg = smc + (ss % NSTG) * STG_BYTES;
        // R pairs for slabs 2ss, 2ss+1
        __half2 rp0 = *(const __half2*)&Rt[(size_t)pl * 64 + 2 * ss];
        __half2 rp8 = *(const __half2*)&Rt[(size_t)(pl + 8) * 64 + 2 * ss];
#pragma unroll
        for (int sl = 0; sl < 2; sl++) {
            const char* Vcur = Vstg + sl * SLAB_BYTES;
            __half2 rlo = sl ? __high2half2(rp0) : __low2half2(rp0);
            __half2 rhi = sl ? __high2half2(rp8) : __low2half2(rp8);
#pragma unroll
            for (int ks = 0; ks < 4; ks++) {
                u32 a0 = h2u(__hmul2(rlo, *(__half2*)&cf[ks][0]));
                u32 a1 = h2u(__hmul2(rhi, *(__half2*)&cf[ks][1]));
                u32 a2 = h2u(__hmul2(rlo, *(__half2*)&cf[ks][2]));
                u32 a3 = h2u(__hmul2(rhi, *(__half2*)&cf[ks][3]));
#pragma unroll
                for (int g = 0; g < 2; g++) {
                    u32 baddr = smem_u32(Vcur + g * (16 * VROWB) + xoff + ks * 32);
                    u32 b0, b1, b2, b3;
                    asm volatile("ldmatrix.sync.aligned.m8n8.x4.shared.b16 {%0,%1,%2,%3}, [%4];"
                                 : "=r"(b0), "=r"(b1), "=r"(b2), "=r"(b3) : "r"(baddr));
                    asm volatile(
                        "mma.sync.aligned.m16n8k16.row.col.f32.f16.f16.f32 "
                        "{%0,%1,%2,%3}, {%4,%5,%6,%7}, {%8,%9}, {%0,%1,%2,%3};"
                        : "+f"(acc[2 * g][0]), "+f"(acc[2 * g][1]),
                          "+f"(acc[2 * g][2]), "+f"(acc[2 * g][3])
                        : "r"(a0), "r"(a1), "r"(a2), "r"(a3), "r"(b0), "r"(b1));
                    asm volatile(
                        "mma.sync.aligned.m16n8k16.row.col.f32.f16.f16.f32 "
                        "{%0,%1,%2,%3}, {%4,%5,%6,%7}, {%8,%9}, {%0,%1,%2,%3};"
                        : "+f"(acc[2 * g + 1][0]), "+f"(acc[2 * g + 1][1]),
                          "+f"(acc[2 * g + 1][2]), "+f"(acc[2 * g + 1][3])
                        : "r"(a0), "r"(a1), "r"(a2), "r"(a3), "r"(b2), "r"(b3));
                }
            }
        }
        if (ss + 2 < 32) ISSUE_STAGE(ss + 2);
        COMMIT();
    }
    asm volatile("cp.async.wait_group 0;");
    __syncthreads();

    // epilogue: transpose through SMEM (Ds overlays V stages), add residual, store
#pragma unroll
    for (int nt = 0; nt < 4; nt++) {
        int d = nt * 8 + qpair * 2;
        Ds[d * 132 + pl]           = acc[nt][0];
        Ds[(d + 1) * 132 + pl]     = acc[nt][1];
        Ds[d * 132 + pl + 8]       = acc[nt][2];
        Ds[(d + 1) * 132 + pl + 8] = acc[nt][3];
    }
    __syncthreads();
#pragma unroll
    for (int u = 0; u < 4; u++) {
        int e = t + u * 256;
        int d = e >> 5, p4 = (e & 31) * 4;
        float4 r = *(const float4*)&Vg[(size_t)d * NPIX + p0 + p4];
        float4 v = *(const float4*)&Ds[d * 132 + p4];
        float4 o = {v.x + r.x, v.y + r.y, v.z + r.z, v.w + r.w};
        *(float4*)&out[((size_t)(b * 256) + H * 32 + d) * NPIX + p0 + p4] = o;
    }
}

extern "C" void kernel_launch(void* const* d_in, const int* in_sizes, int n_in,
                              void* d_out, int out_size) {
    const float* x = (const float*)d_in[0];
    const float* w = (const float*)d_in[1];
    if (n_in >= 2 && in_sizes[0] == OC * DIN) {
        const float* tmp = x; x = w; w = tmp;
    }
    float* out = (float*)d_out;

    k_prep_w<<<(OC * DIN / 2 + 255) / 256, 256>>>(w);
    k_prep_xt<<<dim3(128, 8, BB), 256>>>(x);
    k_projt<<<dim3(64, 10, BB), 256>>>();
    k_qkT<<<dim3(64, NHH, BB), 256>>>();
    k_rowattn<<<dim3(64, NHH, BB), 256>>>();
    k_colattn<<<dim3(64, NHH, BB), 256>>>();
    k_final<<<dim3(32, NHH, BB), 256>>>(out);
}